// round 2
// baseline (speedup 1.0000x reference)
#include <cuda_runtime.h>
#include <math.h>

// Problem constants
#define VOCAB  50257
#define BB     32
#define TT     64
#define EE     256
#define HH     8
#define DD     32
#define LL     8
#define FFN    1024
#define NTOK   (BB*TT)          // 2048
#define EPSLN  1e-5f

// ---------------------------------------------------------------------------
// Scratch
// ---------------------------------------------------------------------------
#define OFF_X    0
#define OFF_QKV  524288
#define OFF_ATT  2097152
#define OFF_H    2621440
#define OFF_Y    4718592
#define OFF_XF   5242880
#define OFF_WT   5767168
#define BUF_TOTAL 7340032

__device__ float g_buf[BUF_TOTAL];

// ---------------------------------------------------------------------------
// Packed f32x2 helpers (FFMA2 — only reachable via PTX)
// ---------------------------------------------------------------------------
__device__ __forceinline__ void ffma2(unsigned long long &d,
                                      unsigned long long a,
                                      unsigned long long b) {
    asm("fma.rn.f32x2 %0, %1, %2, %0;" : "+l"(d) : "l"(a), "l"(b));
}
__device__ __forceinline__ unsigned long long pack2(float x, float y) {
    unsigned long long r;
    asm("mov.b64 %0, {%1, %2};" : "=l"(r) : "f"(x), "f"(y));
    return r;
}
__device__ __forceinline__ void unpack2(unsigned long long v, float &x, float &y) {
    asm("mov.b64 {%0, %1}, %2;" : "=f"(x), "=f"(y) : "l"(v));
}

// ---------------------------------------------------------------------------
// Embedding
// ---------------------------------------------------------------------------
__global__ void embed_kernel(const int* __restrict__ ip,
                             const float* __restrict__ tok,
                             const float* __restrict__ pos,
                             float* __restrict__ x) {
    int row = blockIdx.x;
    int c   = threadIdx.x;
    int t   = row & (TT - 1);
    int v   = ip[row];
    x[row * EE + c] = tok[(size_t)v * EE + c] + pos[t * EE + c];
}

// ---------------------------------------------------------------------------
// One-time transpose of Wq/Wk/Wv [L,H,E,D] -> wt [L, E, 768]
// ---------------------------------------------------------------------------
__global__ void prep_wqkv_kernel(const float* __restrict__ Wq,
                                 const float* __restrict__ Wk,
                                 const float* __restrict__ Wv) {
    int idx = blockIdx.x * blockDim.x + threadIdx.x;
    const int total = LL * EE * 768;
    if (idx >= total) return;
    int l = idx / (EE * 768);
    int r = idx % (EE * 768);
    int c = r / 768;
    int j = r % 768;
    int sel = j >> 8;
    int hd  = j & 255;
    int h = hd >> 5, d = hd & 31;
    const float* W = (sel == 0) ? Wq : (sel == 1) ? Wk : Wv;
    g_buf[OFF_WT + idx] = W[(((size_t)(l * HH + h) * EE + c) * DD) + d];
}

// ---------------------------------------------------------------------------
// Packed-FFMA2 tiled SGEMM: C[M,N] = A[M,K] @ B[K,N] (+bias) (opt relu)
// TN must be even (accumulators are f32x2 pairs along N).
// ---------------------------------------------------------------------------
template<int BM, int BN, int BK, int TM, int TN, bool RELU>
__global__ void __launch_bounds__((BM/TM)*(BN/TN))
sgemm2_kernel(int M, int N, int K,
              const float* __restrict__ A,
              const float* __restrict__ B,
              const float* __restrict__ bias,
              float* __restrict__ C) {
    __shared__ __align__(16) float As[BK][BM];
    __shared__ __align__(16) float Bs[BK][BN];

    constexpr int NTH = (BM/TM)*(BN/TN);
    constexpr int TN2 = TN/2;
    const int tid  = threadIdx.x;
    const int tcol = tid % (BN/TN);
    const int trow = tid / (BN/TN);
    const int brow = blockIdx.y * BM;
    const int bcol = blockIdx.x * BN;

    unsigned long long acc[TM][TN2];
#pragma unroll
    for (int i = 0; i < TM; i++)
#pragma unroll
        for (int j = 0; j < TN2; j++) acc[i][j] = 0ULL;

    for (int k0 = 0; k0 < K; k0 += BK) {
#pragma unroll
        for (int i = tid; i < BM*BK; i += NTH) {
            int r = i / BK, c = i % BK;
            int gr = brow + r;
            As[c][r] = (gr < M) ? A[(size_t)gr * K + k0 + c] : 0.f;
        }
#pragma unroll
        for (int i = tid; i < BK*BN; i += NTH) {
            int r = i / BN, c = i % BN;
            int gc = bcol + c;
            Bs[r][c] = (gc < N) ? B[(size_t)(k0 + r) * N + gc] : 0.f;
        }
        __syncthreads();

#pragma unroll
        for (int kk = 0; kk < BK; kk++) {
            // B fragment: TN consecutive floats as TN/2 packed pairs
            unsigned long long bb[TN2];
            const unsigned long long* bp =
                reinterpret_cast<const unsigned long long*>(&Bs[kk][tcol*TN]);
#pragma unroll
            for (int j = 0; j < TN2; j++) bb[j] = bp[j];
            // A fragment, duplicated into both halves
            const float* ap = &As[kk][trow*TM];
#pragma unroll
            for (int i = 0; i < TM; i++) {
                unsigned long long ad = pack2(ap[i], ap[i]);
#pragma unroll
                for (int j = 0; j < TN2; j++) ffma2(acc[i][j], ad, bb[j]);
            }
        }
        __syncthreads();
    }

    const bool vec_ok = ((N & 1) == 0);
#pragma unroll
    for (int i = 0; i < TM; i++) {
        int gr = brow + trow*TM + i;
        if (gr >= M) continue;
        float* crow = C + (size_t)gr * N;
#pragma unroll
        for (int j = 0; j < TN2; j++) {
            int gc = bcol + tcol*TN + 2*j;
            float lo, hi;
            unpack2(acc[i][j], lo, hi);
            if (bias) {
                if (gc < N)     lo += bias[gc];
                if (gc+1 < N)   hi += bias[gc+1];
            }
            if (RELU) { lo = fmaxf(lo, 0.f); hi = fmaxf(hi, 0.f); }
            if (vec_ok && gc + 1 < N) {
                float2 v; v.x = lo; v.y = hi;
                *reinterpret_cast<float2*>(crow + gc) = v;
            } else {
                if (gc < N)   crow[gc]   = lo;
                if (gc+1 < N) crow[gc+1] = hi;
            }
        }
    }
}

// ---------------------------------------------------------------------------
// Fused causal attention, online softmax, 2 lanes per query.
// grid = B*H blocks, 128 threads. Lane pair (2*qi, 2*qi+1) handles query
// t = warp*16+qi, each lane owning 16 of the 32 head dims.
// ---------------------------------------------------------------------------
__global__ void attn_kernel(const float* __restrict__ qkv,
                            float* __restrict__ att) {
    __shared__ float ks[TT][DD];
    __shared__ float vs[TT][DD];

    int bh = blockIdx.x;
    int b = bh / HH, h = bh % HH;
    int tid = threadIdx.x;  // 0..127

    const float* base = qkv + (size_t)b * TT * 768 + h * DD;
    for (int i = tid; i < TT * DD; i += 128) {
        int s = i >> 5, d = i & 31;
        ks[s][d] = base[s * 768 + 256 + d];
        vs[s][d] = base[s * 768 + 512 + d];
    }

    const int w    = tid >> 5;
    const int lane = tid & 31;
    const int t     = w * 16 + (lane >> 1);
    const int half  = lane & 1;
    const int dbase = half * 16;
    const float scale = 0.17677669529663687f;  // 1/sqrt(32)

    float q[16];
    const float* qp = base + t * 768 + dbase;
#pragma unroll
    for (int dd = 0; dd < 16; dd++) q[dd] = qp[dd] * scale;

    __syncthreads();

    float m = -1e30f, sum = 0.f;
    float o[16];
#pragma unroll
    for (int dd = 0; dd < 16; dd++) o[dd] = 0.f;

    const int tw = w * 16 + 15;  // max query index in this warp
    for (int s = 0; s <= tw; s++) {
        float part = 0.f;
#pragma unroll
        for (int dd = 0; dd < 16; dd++) part += q[dd] * ks[s][dbase + dd];
        float sc = part + __shfl_xor_sync(0xffffffffu, part, 1);
        if (s <= t) {
            float mn   = fmaxf(m, sc);
            float corr = __expf(m - mn);
            float p    = __expf(sc - mn);
            sum = sum * corr + p;
#pragma unroll
            for (int dd = 0; dd < 16; dd++)
                o[dd] = o[dd] * corr + p * vs[s][dbase + dd];
            m = mn;
        }
    }
    float inv = 1.f / sum;
    float* op = att + (size_t)(b * TT + t) * EE + h * DD + dbase;
#pragma unroll
    for (int dd = 0; dd < 16; dd++) op[dd] = o[dd] * inv;
}

// ---------------------------------------------------------------------------
// LayerNorm (optional residual add)
// ---------------------------------------------------------------------------
__global__ void ln_kernel(const float* __restrict__ xin,
                          const float* __restrict__ yin,
                          const float* __restrict__ g,
                          const float* __restrict__ b,
                          float* __restrict__ out) {
    __shared__ float red1[8];
    __shared__ float red2[8];
    int row = blockIdx.x;
    int c   = threadIdx.x;

    float v = xin[(size_t)row * EE + c];
    if (yin) v += yin[(size_t)row * EE + c];

    float s = v;
#pragma unroll
    for (int o = 16; o > 0; o >>= 1) s += __shfl_xor_sync(0xffffffffu, s, o);
    if ((c & 31) == 0) red1[c >> 5] = s;
    __syncthreads();
    float total = 0.f;
#pragma unroll
    for (int i = 0; i < 8; i++) total += red1[i];
    float mean = total * (1.f / EE);

    float d = v - mean;
    float sq = d * d;
#pragma unroll
    for (int o = 16; o > 0; o >>= 1) sq += __shfl_xor_sync(0xffffffffu, sq, o);
    if ((c & 31) == 0) red2[c >> 5] = sq;
    __syncthreads();
    float tsq = 0.f;
#pragma unroll
    for (int i = 0; i < 8; i++) tsq += red2[i];
    float var = tsq * (1.f / EE);

    out[(size_t)row * EE + c] = d * rsqrtf(var + EPSLN) * g[c] + b[c];
}

// ---------------------------------------------------------------------------
// Host orchestration
// ---------------------------------------------------------------------------
extern "C" void kernel_launch(void* const* d_in, const int* in_sizes, int n_in,
                              void* d_out, int out_size) {
    const int*   ip     = (const int*)  d_in[0];
    const float* tok    = (const float*)d_in[1];
    const float* pos    = (const float*)d_in[2];
    const float* Wq     = (const float*)d_in[3];
    const float* Wk     = (const float*)d_in[4];
    const float* Wv     = (const float*)d_in[5];
    const float* Wo     = (const float*)d_in[6];
    const float* bo     = (const float*)d_in[7];
    const float* ln1g   = (const float*)d_in[8];
    const float* ln1b   = (const float*)d_in[9];
    const float* ln2g   = (const float*)d_in[10];
    const float* ln2b   = (const float*)d_in[11];
    const float* W1     = (const float*)d_in[12];
    const float* b1     = (const float*)d_in[13];
    const float* W2     = (const float*)d_in[14];
    const float* b2     = (const float*)d_in[15];
    const float* lnfg   = (const float*)d_in[16];
    const float* lnfb   = (const float*)d_in[17];
    const float* Wlm    = (const float*)d_in[18];
    const float* blm    = (const float*)d_in[19];
    float*       out    = (float*)d_out;

    float* buf = nullptr;
    cudaGetSymbolAddress((void**)&buf, g_buf);
    float* x    = buf + OFF_X;
    float* qkv  = buf + OFF_QKV;
    float* attb = buf + OFF_ATT;
    float* hbuf = buf + OFF_H;
    float* y    = buf + OFF_Y;
    float* xf   = buf + OFF_XF;
    float* wt   = buf + OFF_WT;

    embed_kernel<<<NTOK, EE>>>(ip, tok, pos, x);

    {
        int total = LL * EE * 768;
        prep_wqkv_kernel<<<(total + 255) / 256, 256>>>(Wq, Wk, Wv);
    }

    for (int l = 0; l < LL; l++) {
        // QKV projection: [2048,256]@[256,768]
        {
            dim3 grid(768 / 64, NTOK / 64);
            sgemm2_kernel<64,64,16,4,8,false><<<grid, 128>>>(
                NTOK, 768, EE, x, wt + (size_t)l * EE * 768, nullptr, qkv);
        }
        attn_kernel<<<BB * HH, 128>>>(qkv, attb);
        // Output projection: [2048,256]@[256,256] + bo   (32x64 tiles -> 256 blocks)
        {
            dim3 grid(EE / 64, NTOK / 32);
            sgemm2_kernel<32,64,16,2,8,false><<<grid, 128>>>(
                NTOK, EE, EE, attb, Wo + (size_t)l * EE * EE, bo + l * EE, y);
        }
        ln_kernel<<<NTOK, EE>>>(x, y, ln1g + l * EE, ln1b + l * EE, x);
        // FFN1: relu([2048,256]@[256,1024] + b1)
        {
            dim3 grid(FFN / 64, NTOK / 64);
            sgemm2_kernel<64,64,16,4,8,true><<<grid, 128>>>(
                NTOK, FFN, EE, x, W1 + (size_t)l * EE * FFN, b1 + l * FFN, hbuf);
        }
        // FFN2: [2048,1024]@[1024,256] + b2   (32x64 tiles -> 256 blocks)
        {
            dim3 grid(EE / 64, NTOK / 32);
            sgemm2_kernel<32,64,16,2,8,false><<<grid, 128>>>(
                NTOK, EE, FFN, hbuf, W2 + (size_t)l * FFN * EE, b2 + l * EE, y);
        }
        ln_kernel<<<NTOK, EE>>>(x, y, ln2g + l * EE, ln2b + l * EE, x);
    }

    ln_kernel<<<NTOK, EE>>>(x, nullptr, lnfg, lnfb, xf);

    // LM head: [2048,256]@[256,50257] + blm
    {
        dim3 grid((VOCAB + 127) / 128, NTOK / 128);
        sgemm2_kernel<128,128,16,8,8,false><<<grid, 256>>>(
            NTOK, VOCAB, EE, xf, Wlm, blm, out);
    }
}

// round 5
// speedup vs baseline: 1.0776x; 1.0776x over previous
#include <cuda_runtime.h>
#include <math.h>
#include <stdint.h>

// Problem constants
#define VOCAB  50257
#define BB     32
#define TT     64
#define EE     256
#define HH     8
#define DD     32
#define LL     8
#define FFN    1024
#define NTOK   (BB*TT)          // 2048
#define EPSLN  1e-5f

#define VPAD   50304            // 393*128, multiple of 128 (and of 4)

// ---------------------------------------------------------------------------
// Scratch
// ---------------------------------------------------------------------------
#define OFF_X    0
#define OFF_QKV  524288
#define OFF_ATT  2097152
#define OFF_H    2621440
#define OFF_Y    4718592
#define OFF_XF   5242880
#define OFF_WT   5767168
#define OFF_WLM  7340032                       // padded Wlm [256, VPAD]
#define BUF_TOTAL (7340032 + EE*VPAD)          // + 12,877,824 floats (~80.9 MB)

__device__ float g_buf[BUF_TOTAL];

// ---------------------------------------------------------------------------
// tf32 helpers
// ---------------------------------------------------------------------------
__device__ __forceinline__ float to_tf32(float x) {
    float r;
    asm("cvt.rna.tf32.f32 %0, %1;" : "=f"(r) : "f"(x));
    return r;
}

__device__ __forceinline__ void mma_tf32(float* c, const uint32_t* a, const uint32_t* b) {
    asm volatile(
        "mma.sync.aligned.m16n8k8.row.col.f32.tf32.tf32.f32 "
        "{%0,%1,%2,%3}, {%4,%5,%6,%7}, {%8,%9}, {%0,%1,%2,%3};"
        : "+f"(c[0]), "+f"(c[1]), "+f"(c[2]), "+f"(c[3])
        : "r"(a[0]), "r"(a[1]), "r"(a[2]), "r"(a[3]), "r"(b[0]), "r"(b[1]));
}

// ---------------------------------------------------------------------------
// Embedding
// ---------------------------------------------------------------------------
__global__ void embed_kernel(const int* __restrict__ ip,
                             const float* __restrict__ tok,
                             const float* __restrict__ pos,
                             float* __restrict__ x) {
    int row = blockIdx.x;
    int c   = threadIdx.x;
    int t   = row & (TT - 1);
    int v   = ip[row];
    x[row * EE + c] = tok[(size_t)v * EE + c] + pos[t * EE + c];
}

// ---------------------------------------------------------------------------
// Transpose Wq/Wk/Wv [L,H,E,D] -> wt [L, E, 768]
// ---------------------------------------------------------------------------
__global__ void prep_wqkv_kernel(const float* __restrict__ Wq,
                                 const float* __restrict__ Wk,
                                 const float* __restrict__ Wv) {
    int idx = blockIdx.x * blockDim.x + threadIdx.x;
    const int total = LL * EE * 768;
    if (idx >= total) return;
    int l = idx / (EE * 768);
    int r = idx % (EE * 768);
    int c = r / 768;
    int j = r % 768;
    int sel = j >> 8;
    int hd  = j & 255;
    int h = hd >> 5, d = hd & 31;
    const float* W = (sel == 0) ? Wq : (sel == 1) ? Wk : Wv;
    g_buf[OFF_WT + idx] = W[(((size_t)(l * HH + h) * EE + c) * DD) + d];
}

// ---------------------------------------------------------------------------
// Pad-copy Wlm [256, VOCAB] -> g_buf[OFF_WLM] [256, VPAD] (zero pad cols)
// ---------------------------------------------------------------------------
__global__ void prep_wlm_kernel(const float* __restrict__ Wlm) {
    size_t idx = (size_t)blockIdx.x * blockDim.x + threadIdx.x;
    const size_t total = (size_t)EE * VPAD;
    if (idx >= total) return;
    int k = (int)(idx / VPAD);
    int n = (int)(idx % VPAD);
    g_buf[OFF_WLM + idx] = (n < VOCAB) ? Wlm[(size_t)k * VOCAB + n] : 0.f;
}

// ---------------------------------------------------------------------------
// 3xTF32 warp-MMA GEMM: C[M,N] = A[M,K] @ B[K,:] (+bias) (opt relu)
// A row-major (K stride), B row-major with row stride ldb (ldb % 4 == 0,
// and caller guarantees bcol+BN <= ldb with pad region zeroed).
// Each operand split v = hi + lo (tf32-exact); acc = hi*hi + hi*lo + lo*hi.
// ---------------------------------------------------------------------------
template<int BM, int BN, int WM, int WN, bool RELU>
__global__ void __launch_bounds__((BM/WM)*(BN/WN)*32, 1)
mma_gemm_kernel(int M, int N, int K, int ldb,
                const float* __restrict__ A,
                const float* __restrict__ B,
                const float* __restrict__ bias,
                float* __restrict__ C) {
    constexpr int BK  = 16;
    constexpr int LDS_ = BK + 4;               // 20 floats: conflict-free frags
    constexpr int NW  = (BM/WM)*(BN/WN);
    constexpr int NTH = NW * 32;
    constexpr int MT  = WM / 16;
    constexpr int NT  = WN / 8;

    __shared__ float Ah[BM][LDS_], Al[BM][LDS_];
    __shared__ float Bh[BN][LDS_], Bl[BN][LDS_];

    const int tid  = threadIdx.x;
    const int w    = tid >> 5;
    const int lane = tid & 31;
    const int g    = lane >> 2;
    const int t    = lane & 3;
    const int wm   = (w / (BN/WN)) * WM;
    const int wn   = (w % (BN/WN)) * WN;
    const int brow = blockIdx.x * BM;
    const int bcol = blockIdx.y * BN;
    const bool nedge = (bcol + BN > N);

    float acc[MT][NT][4];
#pragma unroll
    for (int i = 0; i < MT; i++)
#pragma unroll
        for (int j = 0; j < NT; j++)
#pragma unroll
            for (int q = 0; q < 4; q++) acc[i][j][q] = 0.f;

    for (int k0 = 0; k0 < K; k0 += BK) {
        // ---- load A tile (BM x 16), split hi/lo ----
#pragma unroll
        for (int f = tid; f < BM * 4; f += NTH) {
            int row = f >> 2;
            int k   = (f & 3) << 2;
            float4 v = *reinterpret_cast<const float4*>(
                A + (size_t)(brow + row) * K + k0 + k);
            float h0 = to_tf32(v.x), h1 = to_tf32(v.y),
                  h2 = to_tf32(v.z), h3 = to_tf32(v.w);
            Ah[row][k+0] = h0; Al[row][k+0] = to_tf32(v.x - h0);
            Ah[row][k+1] = h1; Al[row][k+1] = to_tf32(v.y - h1);
            Ah[row][k+2] = h2; Al[row][k+2] = to_tf32(v.z - h2);
            Ah[row][k+3] = h3; Al[row][k+3] = to_tf32(v.w - h3);
        }
        // ---- load B tile (16 x BN) transposed into [n][k], split hi/lo ----
#pragma unroll
        for (int f = tid; f < 4 * BN; f += NTH) {
            int n4 = f % (BN/4);
            int kr = f / (BN/4);
            int n  = n4 * 4;
            float4 v = *reinterpret_cast<const float4*>(
                B + (size_t)(k0 + kr) * ldb + bcol + n);
            float h0 = to_tf32(v.x), h1 = to_tf32(v.y),
                  h2 = to_tf32(v.z), h3 = to_tf32(v.w);
            Bh[n+0][kr] = h0; Bl[n+0][kr] = to_tf32(v.x - h0);
            Bh[n+1][kr] = h1; Bl[n+1][kr] = to_tf32(v.y - h1);
            Bh[n+2][kr] = h2; Bl[n+2][kr] = to_tf32(v.z - h2);
            Bh[n+3][kr] = h3; Bl[n+3][kr] = to_tf32(v.w - h3);
        }
        __syncthreads();

#pragma unroll
        for (int kk = 0; kk < BK; kk += 8) {
            uint32_t afh[MT][4], afl[MT][4];
            uint32_t bfh[NT][2], bfl[NT][2];
#pragma unroll
            for (int mt = 0; mt < MT; mt++) {
                int r = wm + mt*16 + g;
                afh[mt][0] = __float_as_uint(Ah[r  ][kk + t]);
                afh[mt][1] = __float_as_uint(Ah[r+8][kk + t]);
                afh[mt][2] = __float_as_uint(Ah[r  ][kk + t + 4]);
                afh[mt][3] = __float_as_uint(Ah[r+8][kk + t + 4]);
                afl[mt][0] = __float_as_uint(Al[r  ][kk + t]);
                afl[mt][1] = __float_as_uint(Al[r+8][kk + t]);
                afl[mt][2] = __float_as_uint(Al[r  ][kk + t + 4]);
                afl[mt][3] = __float_as_uint(Al[r+8][kk + t + 4]);
            }
#pragma unroll
            for (int nt = 0; nt < NT; nt++) {
                int n = wn + nt*8 + g;
                bfh[nt][0] = __float_as_uint(Bh[n][kk + t]);
                bfh[nt][1] = __float_as_uint(Bh[n][kk + t + 4]);
                bfl[nt][0] = __float_as_uint(Bl[n][kk + t]);
                bfl[nt][1] = __float_as_uint(Bl[n][kk + t + 4]);
            }
#pragma unroll
            for (int mt = 0; mt < MT; mt++)
#pragma unroll
                for (int nt = 0; nt < NT; nt++) {
                    mma_tf32(acc[mt][nt], afh[mt], bfl[nt]);
                    mma_tf32(acc[mt][nt], afl[mt], bfh[nt]);
                    mma_tf32(acc[mt][nt], afh[mt], bfh[nt]);
                }
        }
        __syncthreads();
    }

    // ---- epilogue ----
    const bool scalar_store = nedge || (N & 1);
#pragma unroll
    for (int mt = 0; mt < MT; mt++) {
        int r0 = brow + wm + mt*16 + g;
        int r1 = r0 + 8;
#pragma unroll
        for (int nt = 0; nt < NT; nt++) {
            int c0 = bcol + wn + nt*8 + 2*t;
            float v0 = acc[mt][nt][0], v1 = acc[mt][nt][1];
            float v2 = acc[mt][nt][2], v3 = acc[mt][nt][3];
            if (bias) {
                float b0 = (c0   < N) ? bias[c0]   : 0.f;
                float b1 = (c0+1 < N) ? bias[c0+1] : 0.f;
                v0 += b0; v1 += b1; v2 += b0; v3 += b1;
            }
            if (RELU) {
                v0 = fmaxf(v0, 0.f); v1 = fmaxf(v1, 0.f);
                v2 = fmaxf(v2, 0.f); v3 = fmaxf(v3, 0.f);
            }
            if (!scalar_store) {
                float2 p0; p0.x = v0; p0.y = v1;
                float2 p1; p1.x = v2; p1.y = v3;
                *reinterpret_cast<float2*>(C + (size_t)r0 * N + c0) = p0;
                *reinterpret_cast<float2*>(C + (size_t)r1 * N + c0) = p1;
            } else {
                if (c0   < N) { C[(size_t)r0*N + c0]   = v0; C[(size_t)r1*N + c0]   = v2; }
                if (c0+1 < N) { C[(size_t)r0*N + c0+1] = v1; C[(size_t)r1*N + c0+1] = v3; }
            }
        }
    }
}

// ---------------------------------------------------------------------------
// Fused causal attention (online softmax, 2 lanes/query)
// ---------------------------------------------------------------------------
__global__ void attn_kernel(const float* __restrict__ qkv,
                            float* __restrict__ att) {
    __shared__ float ks[TT][DD];
    __shared__ float vs[TT][DD];

    int bh = blockIdx.x;
    int b = bh / HH, h = bh % HH;
    int tid = threadIdx.x;

    const float* base = qkv + (size_t)b * TT * 768 + h * DD;
    for (int i = tid; i < TT * DD; i += 128) {
        int s = i >> 5, d = i & 31;
        ks[s][d] = base[s * 768 + 256 + d];
        vs[s][d] = base[s * 768 + 512 + d];
    }

    const int w    = tid >> 5;
    const int lane = tid & 31;
    const int t     = w * 16 + (lane >> 1);
    const int half  = lane & 1;
    const int dbase = half * 16;
    const float scale = 0.17677669529663687f;

    float q[16];
    const float* qp = base + t * 768 + dbase;
#pragma unroll
    for (int dd = 0; dd < 16; dd++) q[dd] = qp[dd] * scale;

    __syncthreads();

    float m = -1e30f, sum = 0.f;
    float o[16];
#pragma unroll
    for (int dd = 0; dd < 16; dd++) o[dd] = 0.f;

    const int tw = w * 16 + 15;
    for (int s = 0; s <= tw; s++) {
        float part = 0.f;
#pragma unroll
        for (int dd = 0; dd < 16; dd++) part += q[dd] * ks[s][dbase + dd];
        float sc = part + __shfl_xor_sync(0xffffffffu, part, 1);
        if (s <= t) {
            float mn   = fmaxf(m, sc);
            float corr = __expf(m - mn);
            float p    = __expf(sc - mn);
            sum = sum * corr + p;
#pragma unroll
            for (int dd = 0; dd < 16; dd++)
                o[dd] = o[dd] * corr + p * vs[s][dbase + dd];
            m = mn;
        }
    }
    float inv = 1.f / sum;
    float* op = att + (size_t)(b * TT + t) * EE + h * DD + dbase;
#pragma unroll
    for (int dd = 0; dd < 16; dd++) op[dd] = o[dd] * inv;
}

// ---------------------------------------------------------------------------
// LayerNorm (optional residual add)
// ---------------------------------------------------------------------------
__global__ void ln_kernel(const float* __restrict__ xin,
                          const float* __restrict__ yin,
                          const float* __restrict__ g,
                          const float* __restrict__ b,
                          float* __restrict__ out) {
    __shared__ float red1[8];
    __shared__ float red2[8];
    int row = blockIdx.x;
    int c   = threadIdx.x;

    float v = xin[(size_t)row * EE + c];
    if (yin) v += yin[(size_t)row * EE + c];

    float s = v;
#pragma unroll
    for (int o = 16; o > 0; o >>= 1) s += __shfl_xor_sync(0xffffffffu, s, o);
    if ((c & 31) == 0) red1[c >> 5] = s;
    __syncthreads();
    float total = 0.f;
#pragma unroll
    for (int i = 0; i < 8; i++) total += red1[i];
    float mean = total * (1.f / EE);

    float d = v - mean;
    float sq = d * d;
#pragma unroll
    for (int o = 16; o > 0; o >>= 1) sq += __shfl_xor_sync(0xffffffffu, sq, o);
    if ((c & 31) == 0) red2[c >> 5] = sq;
    __syncthreads();
    float tsq = 0.f;
#pragma unroll
    for (int i = 0; i < 8; i++) tsq += red2[i];
    float var = tsq * (1.f / EE);

    out[(size_t)row * EE + c] = d * rsqrtf(var + EPSLN) * g[c] + b[c];
}

// ---------------------------------------------------------------------------
// Host orchestration
// ---------------------------------------------------------------------------
extern "C" void kernel_launch(void* const* d_in, const int* in_sizes, int n_in,
                              void* d_out, int out_size) {
    const int*   ip     = (const int*)  d_in[0];
    const float* tok    = (const float*)d_in[1];
    const float* pos    = (const float*)d_in[2];
    const float* Wq     = (const float*)d_in[3];
    const float* Wk     = (const float*)d_in[4];
    const float* Wv     = (const float*)d_in[5];
    const float* Wo     = (const float*)d_in[6];
    const float* bo     = (const float*)d_in[7];
    const float* ln1g   = (const float*)d_in[8];
    const float* ln1b   = (const float*)d_in[9];
    const float* ln2g   = (const float*)d_in[10];
    const float* ln2b   = (const float*)d_in[11];
    const float* W1     = (const float*)d_in[12];
    const float* b1     = (const float*)d_in[13];
    const float* W2     = (const float*)d_in[14];
    const float* b2     = (const float*)d_in[15];
    const float* lnfg   = (const float*)d_in[16];
    const float* lnfb   = (const float*)d_in[17];
    const float* Wlm    = (const float*)d_in[18];
    const float* blm    = (const float*)d_in[19];
    float*       out    = (float*)d_out;

    float* buf = nullptr;
    cudaGetSymbolAddress((void**)&buf, g_buf);
    float* x    = buf + OFF_X;
    float* qkv  = buf + OFF_QKV;
    float* attb = buf + OFF_ATT;
    float* hbuf = buf + OFF_H;
    float* y    = buf + OFF_Y;
    float* xf   = buf + OFF_XF;
    float* wt   = buf + OFF_WT;
    float* wlm  = buf + OFF_WLM;

    embed_kernel<<<NTOK, EE>>>(ip, tok, pos, x);

    {
        int total = LL * EE * 768;
        prep_wqkv_kernel<<<(total + 255) / 256, 256>>>(Wq, Wk, Wv);
    }
    {
        size_t total = (size_t)EE * VPAD;
        prep_wlm_kernel<<<(unsigned)((total + 255) / 256), 256>>>(Wlm);
    }

    for (int l = 0; l < LL; l++) {
        // QKV projection: [2048,256]@[256,768]
        {
            dim3 grid(NTOK / 64, 768 / 64);
            mma_gemm_kernel<64,64,32,32,false><<<grid, 128>>>(
                NTOK, 768, EE, 768, x, wt + (size_t)l * EE * 768, nullptr, qkv);
        }
        attn_kernel<<<BB * HH, 128>>>(qkv, attb);
        // Output projection: [2048,256]@[256,256] + bo
        {
            dim3 grid(NTOK / 64, EE / 64);
            mma_gemm_kernel<64,64,32,32,false><<<grid, 128>>>(
                NTOK, EE, EE, EE, attb, Wo + (size_t)l * EE * EE, bo + l * EE, y);
        }
        ln_kernel<<<NTOK, EE>>>(x, y, ln1g + l * EE, ln1b + l * EE, x);
        // FFN1: relu([2048,256]@[256,1024] + b1)
        {
            dim3 grid(NTOK / 64, FFN / 64);
            mma_gemm_kernel<64,64,32,32,true><<<grid, 128>>>(
                NTOK, FFN, EE, FFN, x, W1 + (size_t)l * EE * FFN, b1 + l * FFN, hbuf);
        }
        // FFN2: [2048,1024]@[1024,256] + b2
        {
            dim3 grid(NTOK / 64, EE / 64);
            mma_gemm_kernel<64,64,32,32,false><<<grid, 128>>>(
                NTOK, EE, FFN, EE, hbuf, W2 + (size_t)l * FFN * EE, b2 + l * EE, y);
        }
        ln_kernel<<<NTOK, EE>>>(x, y, ln2g + l * EE, ln2b + l * EE, x);
    }

    ln_kernel<<<NTOK, EE>>>(x, nullptr, lnfg, lnfb, xf);

    // LM head: [2048,256]@[256,50257] + blm  (padded B, ldb=VPAD; M tiles fastest)
    {
        dim3 grid(NTOK / 128, VPAD / 128);
        mma_gemm_kernel<128,128,64,32,false><<<grid, 256>>>(
            NTOK, VOCAB, EE, VPAD, xf, wlm, blm, out);
    }
}

// round 11
// speedup vs baseline: 2.7297x; 2.5332x over previous
#include <cuda_runtime.h>
#include <cuda_bf16.h>
#include <math.h>
#include <stdint.h>

// Problem constants
#define VOCAB  50257
#define BB     32
#define TT     64
#define EE     256
#define HH     8
#define DD     32
#define LL     8
#define FFN    1024
#define NTOK   (BB*TT)          // 2048
#define EPSLN  1e-5f

#define VPAD   50304            // 393*128

// ---------------------------------------------------------------------------
// Scratch
// ---------------------------------------------------------------------------
#define OFF_X    0
#define OFF_QKV  524288
#define OFF_ATT  2097152
#define OFF_H    2621440
#define OFF_Y    4718592
#define OFF_XF   5242880
#define OFF_WT   5767168
#define OFF_WLM  7340032                       // padded Wlm [256, VPAD]
#define BUF_TOTAL (7340032 + EE*VPAD)

__device__ float g_buf[BUF_TOTAL];

// ---------------------------------------------------------------------------
// bf16 split + MMA helpers
// ---------------------------------------------------------------------------
__device__ __forceinline__ void bsplit(float x, __nv_bfloat16 &h, __nv_bfloat16 &l) {
    h = __float2bfloat16_rn(x);
    l = __float2bfloat16_rn(x - __bfloat162float(h));
}

__device__ __forceinline__ void ldmx4(uint32_t* r, uint32_t saddr) {
    asm volatile("ldmatrix.sync.aligned.m8n8.x4.shared.b16 {%0,%1,%2,%3}, [%4];"
        : "=r"(r[0]), "=r"(r[1]), "=r"(r[2]), "=r"(r[3]) : "r"(saddr));
}
__device__ __forceinline__ void ldmx4t(uint32_t* r, uint32_t saddr) {
    asm volatile("ldmatrix.sync.aligned.m8n8.x4.trans.shared.b16 {%0,%1,%2,%3}, [%4];"
        : "=r"(r[0]), "=r"(r[1]), "=r"(r[2]), "=r"(r[3]) : "r"(saddr));
}
__device__ __forceinline__ void mma_bf16(float* c, const uint32_t* a,
                                         uint32_t b0, uint32_t b1) {
    asm volatile(
        "mma.sync.aligned.m16n8k16.row.col.f32.bf16.bf16.f32 "
        "{%0,%1,%2,%3}, {%4,%5,%6,%7}, {%8,%9}, {%0,%1,%2,%3};"
        : "+f"(c[0]), "+f"(c[1]), "+f"(c[2]), "+f"(c[3])
        : "r"(a[0]), "r"(a[1]), "r"(a[2]), "r"(a[3]), "r"(b0), "r"(b1));
}

// ---------------------------------------------------------------------------
// Embedding
// ---------------------------------------------------------------------------
__global__ void embed_kernel(const int* __restrict__ ip,
                             const float* __restrict__ tok,
                             const float* __restrict__ pos,
                             float* __restrict__ x) {
    int row = blockIdx.x;
    int c   = threadIdx.x;
    int t   = row & (TT - 1);
    int v   = ip[row];
    x[row * EE + c] = tok[(size_t)v * EE + c] + pos[t * EE + c];
}

// ---------------------------------------------------------------------------
// Transpose Wq/Wk/Wv [L,H,E,D] -> wt [L, E, 768]
// ---------------------------------------------------------------------------
__global__ void prep_wqkv_kernel(const float* __restrict__ Wq,
                                 const float* __restrict__ Wk,
                                 const float* __restrict__ Wv) {
    int idx = blockIdx.x * blockDim.x + threadIdx.x;
    const int total = LL * EE * 768;
    if (idx >= total) return;
    int l = idx / (EE * 768);
    int r = idx % (EE * 768);
    int c = r / 768;
    int j = r % 768;
    int sel = j >> 8;
    int hd  = j & 255;
    int h = hd >> 5, d = hd & 31;
    const float* W = (sel == 0) ? Wq : (sel == 1) ? Wk : Wv;
    g_buf[OFF_WT + idx] = W[(((size_t)(l * HH + h) * EE + c) * DD) + d];
}

// ---------------------------------------------------------------------------
// Pad-copy Wlm [256, VOCAB] -> [256, VPAD] (zero pad)
// ---------------------------------------------------------------------------
__global__ void prep_wlm_kernel(const float* __restrict__ Wlm) {
    size_t idx = (size_t)blockIdx.x * blockDim.x + threadIdx.x;
    const size_t total = (size_t)EE * VPAD;
    if (idx >= total) return;
    int k = (int)(idx / VPAD);
    int n = (int)(idx % VPAD);
    g_buf[OFF_WLM + idx] = (n < VOCAB) ? Wlm[(size_t)k * VOCAB + n] : 0.f;
}

// ---------------------------------------------------------------------------
// 3xBF16 warp-MMA GEMM with ldmatrix:
// C[M,N] = A[M,K] @ B[K,:] (+bias) (opt relu)
// A row-major (stride K), B row-major (stride ldb; ldb%4==0, grid cols padded).
// v = hi + lo (both bf16); acc = hi*hi + hi*lo + lo*hi in fp32.
// A tiles smem [m][k] stride BK+8; B tiles smem [k][n] stride BN+8 —
// both strides give conflict-free ldmatrix row addressing (distinct mod 128B).
// ---------------------------------------------------------------------------
template<int BM, int BN, int WM, int WN, bool RELU>
__global__ void __launch_bounds__((BM/WM)*(BN/WN)*32)
bf16_gemm_kernel(int M, int N, int K, int ldb,
                 const float* __restrict__ A,
                 const float* __restrict__ B,
                 const float* __restrict__ bias,
                 float* __restrict__ C) {
    constexpr int BK   = 32;
    constexpr int ASTR = BK + 8;     // bf16 elems; 80 B rows
    constexpr int BSTR = BN + 8;
    constexpr int NW   = (BM/WM)*(BN/WN);
    constexpr int NTH  = NW * 32;
    constexpr int MT   = WM / 16;
    constexpr int NT   = WN / 8;
    static_assert(NT % 2 == 0, "NT must be even for x4.trans B loads");

    __shared__ __nv_bfloat16 Ah[BM * ASTR], Al[BM * ASTR];
    __shared__ __nv_bfloat16 Bh[BK * BSTR], Bl[BK * BSTR];

    const int tid  = threadIdx.x;
    const int w    = tid >> 5;
    const int lane = tid & 31;
    const int g    = lane >> 2;
    const int t    = lane & 3;
    const int wm   = (w / (BN/WN)) * WM;
    const int wn   = (w % (BN/WN)) * WN;
    const int brow = blockIdx.x * BM;
    const int bcol = blockIdx.y * BN;
    const bool nedge = (bcol + BN > N);

    const uint32_t ah_b = (uint32_t)__cvta_generic_to_shared(Ah);
    const uint32_t al_b = (uint32_t)__cvta_generic_to_shared(Al);
    const uint32_t bh_b = (uint32_t)__cvta_generic_to_shared(Bh);
    const uint32_t bl_b = (uint32_t)__cvta_generic_to_shared(Bl);

    float acc[MT][NT][4];
#pragma unroll
    for (int i = 0; i < MT; i++)
#pragma unroll
        for (int j = 0; j < NT; j++)
#pragma unroll
            for (int q = 0; q < 4; q++) acc[i][j][q] = 0.f;

    // per-lane ldmatrix address components
    const uint32_t a_row_off = (uint32_t)(lane & 15) * (ASTR * 2);
    const uint32_t a_col_off = (uint32_t)((lane >> 4) << 3) * 2;
    const uint32_t b_row_off = (uint32_t)(lane & 15) * (BSTR * 2);
    const uint32_t b_col_off = (uint32_t)(wn + ((lane >> 4) << 3)) * 2;

    for (int k0 = 0; k0 < K; k0 += BK) {
        // ---- A tile: BM x 32 floats -> bf16 hi/lo ----
#pragma unroll
        for (int f = tid; f < BM * 8; f += NTH) {
            int row = f >> 3, kq = (f & 7) << 2;
            float4 v = *reinterpret_cast<const float4*>(
                A + (size_t)(brow + row) * K + k0 + kq);
            __nv_bfloat16 h0,h1,h2,h3,l0,l1,l2,l3;
            bsplit(v.x,h0,l0); bsplit(v.y,h1,l1); bsplit(v.z,h2,l2); bsplit(v.w,h3,l3);
            __nv_bfloat162* ph = reinterpret_cast<__nv_bfloat162*>(&Ah[row*ASTR + kq]);
            __nv_bfloat162* pl = reinterpret_cast<__nv_bfloat162*>(&Al[row*ASTR + kq]);
            ph[0] = __nv_bfloat162(h0, h1); ph[1] = __nv_bfloat162(h2, h3);
            pl[0] = __nv_bfloat162(l0, l1); pl[1] = __nv_bfloat162(l2, l3);
        }
        // ---- B tile: 32 x BN floats -> bf16 hi/lo, kept [k][n] ----
#pragma unroll
        for (int f = tid; f < 8 * BN; f += NTH) {
            int kr = f / (BN/4);
            int n  = (f % (BN/4)) << 2;
            float4 v = *reinterpret_cast<const float4*>(
                B + (size_t)(k0 + kr) * ldb + bcol + n);
            __nv_bfloat16 h0,h1,h2,h3,l0,l1,l2,l3;
            bsplit(v.x,h0,l0); bsplit(v.y,h1,l1); bsplit(v.z,h2,l2); bsplit(v.w,h3,l3);
            __nv_bfloat162* ph = reinterpret_cast<__nv_bfloat162*>(&Bh[kr*BSTR + n]);
            __nv_bfloat162* pl = reinterpret_cast<__nv_bfloat162*>(&Bl[kr*BSTR + n]);
            ph[0] = __nv_bfloat162(h0, h1); ph[1] = __nv_bfloat162(h2, h3);
            pl[0] = __nv_bfloat162(l0, l1); pl[1] = __nv_bfloat162(l2, l3);
        }
        __syncthreads();

#pragma unroll
        for (int kk = 0; kk < BK; kk += 16) {
            uint32_t afh[MT][4], afl[MT][4];
#pragma unroll
            for (int mt = 0; mt < MT; mt++) {
                uint32_t off = (uint32_t)(wm + mt*16) * (ASTR*2)
                             + a_row_off + (uint32_t)kk*2 + a_col_off;
                ldmx4(afh[mt], ah_b + off);
                ldmx4(afl[mt], al_b + off);
            }
            uint32_t bfh[NT][2], bfl[NT][2];
#pragma unroll
            for (int ntp = 0; ntp < NT/2; ntp++) {
                uint32_t off = (uint32_t)kk * (BSTR*2) + b_row_off
                             + (uint32_t)(ntp*16)*2 + b_col_off;
                uint32_t r4[4];
                ldmx4t(r4, bh_b + off);
                bfh[2*ntp][0] = r4[0]; bfh[2*ntp][1] = r4[1];
                bfh[2*ntp+1][0] = r4[2]; bfh[2*ntp+1][1] = r4[3];
                ldmx4t(r4, bl_b + off);
                bfl[2*ntp][0] = r4[0]; bfl[2*ntp][1] = r4[1];
                bfl[2*ntp+1][0] = r4[2]; bfl[2*ntp+1][1] = r4[3];
            }
#pragma unroll
            for (int mt = 0; mt < MT; mt++)
#pragma unroll
                for (int nt = 0; nt < NT; nt++) {
                    mma_bf16(acc[mt][nt], afh[mt], bfl[nt][0], bfl[nt][1]);
                    mma_bf16(acc[mt][nt], afl[mt], bfh[nt][0], bfh[nt][1]);
                    mma_bf16(acc[mt][nt], afh[mt], bfh[nt][0], bfh[nt][1]);
                }
        }
        __syncthreads();
    }

    // ---- epilogue ----
    const bool scalar_store = nedge || (N & 1);
#pragma unroll
    for (int mt = 0; mt < MT; mt++) {
        int r0 = brow + wm + mt*16 + g;
        int r1 = r0 + 8;
#pragma unroll
        for (int nt = 0; nt < NT; nt++) {
            int c0 = bcol + wn + nt*8 + 2*t;
            float v0 = acc[mt][nt][0], v1 = acc[mt][nt][1];
            float v2 = acc[mt][nt][2], v3 = acc[mt][nt][3];
            if (bias) {
                float b0 = (c0   < N) ? bias[c0]   : 0.f;
                float b1 = (c0+1 < N) ? bias[c0+1] : 0.f;
                v0 += b0; v1 += b1; v2 += b0; v3 += b1;
            }
            if (RELU) {
                v0 = fmaxf(v0, 0.f); v1 = fmaxf(v1, 0.f);
                v2 = fmaxf(v2, 0.f); v3 = fmaxf(v3, 0.f);
            }
            if (!scalar_store) {
                float2 p0; p0.x = v0; p0.y = v1;
                float2 p1; p1.x = v2; p1.y = v3;
                *reinterpret_cast<float2*>(C + (size_t)r0 * N + c0) = p0;
                *reinterpret_cast<float2*>(C + (size_t)r1 * N + c0) = p1;
            } else {
                if (c0   < N) { C[(size_t)r0*N + c0]   = v0; C[(size_t)r1*N + c0]   = v2; }
                if (c0+1 < N) { C[(size_t)r0*N + c0+1] = v1; C[(size_t)r1*N + c0+1] = v3; }
            }
        }
    }
}

// ---------------------------------------------------------------------------
// Fused causal attention (online softmax, 2 lanes/query)
// ---------------------------------------------------------------------------
__global__ void attn_kernel(const float* __restrict__ qkv,
                            float* __restrict__ att) {
    __shared__ float ks[TT][DD];
    __shared__ float vs[TT][DD];

    int bh = blockIdx.x;
    int b = bh / HH, h = bh % HH;
    int tid = threadIdx.x;

    const float* base = qkv + (size_t)b * TT * 768 + h * DD;
    for (int i = tid; i < TT * DD; i += 128) {
        int s = i >> 5, d = i & 31;
        ks[s][d] = base[s * 768 + 256 + d];
        vs[s][d] = base[s * 768 + 512 + d];
    }

    const int w    = tid >> 5;
    const int lane = tid & 31;
    const int t     = w * 16 + (lane >> 1);
    const int half  = lane & 1;
    const int dbase = half * 16;
    const float scale = 0.17677669529663687f;

    float q[16];
    const float* qp = base + t * 768 + dbase;
#pragma unroll
    for (int dd = 0; dd < 16; dd++) q[dd] = qp[dd] * scale;

    __syncthreads();

    float m = -1e30f, sum = 0.f;
    float o[16];
#pragma unroll
    for (int dd = 0; dd < 16; dd++) o[dd] = 0.f;

    const int tw = w * 16 + 15;
    for (int s = 0; s <= tw; s++) {
        float part = 0.f;
#pragma unroll
        for (int dd = 0; dd < 16; dd++) part += q[dd] * ks[s][dbase + dd];
        float sc = part + __shfl_xor_sync(0xffffffffu, part, 1);
        if (s <= t) {
            float mn   = fmaxf(m, sc);
            float corr = __expf(m - mn);
            float p    = __expf(sc - mn);
            sum = sum * corr + p;
#pragma unroll
            for (int dd = 0; dd < 16; dd++)
                o[dd] = o[dd] * corr + p * vs[s][dbase + dd];
            m = mn;
        }
    }
    float inv = 1.f / sum;
    float* op = att + (size_t)(b * TT + t) * EE + h * DD + dbase;
#pragma unroll
    for (int dd = 0; dd < 16; dd++) op[dd] = o[dd] * inv;
}

// ---------------------------------------------------------------------------
// LayerNorm (optional residual add)
// ---------------------------------------------------------------------------
__global__ void ln_kernel(const float* __restrict__ xin,
                          const float* __restrict__ yin,
                          const float* __restrict__ g,
                          const float* __restrict__ b,
                          float* __restrict__ out) {
    __shared__ float red1[8];
    __shared__ float red2[8];
    int row = blockIdx.x;
    int c   = threadIdx.x;

    float v = xin[(size_t)row * EE + c];
    if (yin) v += yin[(size_t)row * EE + c];

    float s = v;
#pragma unroll
    for (int o = 16; o > 0; o >>= 1) s += __shfl_xor_sync(0xffffffffu, s, o);
    if ((c & 31) == 0) red1[c >> 5] = s;
    __syncthreads();
    float total = 0.f;
#pragma unroll
    for (int i = 0; i < 8; i++) total += red1[i];
    float mean = total * (1.f / EE);

    float d = v - mean;
    float sq = d * d;
#pragma unroll
    for (int o = 16; o > 0; o >>= 1) sq += __shfl_xor_sync(0xffffffffu, sq, o);
    if ((c & 31) == 0) red2[c >> 5] = sq;
    __syncthreads();
    float tsq = 0.f;
#pragma unroll
    for (int i = 0; i < 8; i++) tsq += red2[i];
    float var = tsq * (1.f / EE);

    out[(size_t)row * EE + c] = d * rsqrtf(var + EPSLN) * g[c] + b[c];
}

// ---------------------------------------------------------------------------
// Host orchestration
// ---------------------------------------------------------------------------
extern "C" void kernel_launch(void* const* d_in, const int* in_sizes, int n_in,
                              void* d_out, int out_size) {
    const int*   ip     = (const int*)  d_in[0];
    const float* tok    = (const float*)d_in[1];
    const float* pos    = (const float*)d_in[2];
    const float* Wq     = (const float*)d_in[3];
    const float* Wk     = (const float*)d_in[4];
    const float* Wv     = (const float*)d_in[5];
    const float* Wo     = (const float*)d_in[6];
    const float* bo     = (const float*)d_in[7];
    const float* ln1g   = (const float*)d_in[8];
    const float* ln1b   = (const float*)d_in[9];
    const float* ln2g   = (const float*)d_in[10];
    const float* ln2b   = (const float*)d_in[11];
    const float* W1     = (const float*)d_in[12];
    const float* b1     = (const float*)d_in[13];
    const float* W2     = (const float*)d_in[14];
    const float* b2     = (const float*)d_in[15];
    const float* lnfg   = (const float*)d_in[16];
    const float* lnfb   = (const float*)d_in[17];
    const float* Wlm    = (const float*)d_in[18];
    const float* blm    = (const float*)d_in[19];
    float*       out    = (float*)d_out;

    float* buf = nullptr;
    cudaGetSymbolAddress((void**)&buf, g_buf);
    float* x    = buf + OFF_X;
    float* qkv  = buf + OFF_QKV;
    float* attb = buf + OFF_ATT;
    float* hbuf = buf + OFF_H;
    float* y    = buf + OFF_Y;
    float* xf   = buf + OFF_XF;
    float* wt   = buf + OFF_WT;
    float* wlm  = buf + OFF_WLM;

    embed_kernel<<<NTOK, EE>>>(ip, tok, pos, x);

    {
        int total = LL * EE * 768;
        prep_wqkv_kernel<<<(total + 255) / 256, 256>>>(Wq, Wk, Wv);
    }
    {
        size_t total = (size_t)EE * VPAD;
        prep_wlm_kernel<<<(unsigned)((total + 255) / 256), 256>>>(Wlm);
    }

    for (int l = 0; l < LL; l++) {
        // QKV projection: [2048,256]@[256,768]
        {
            dim3 grid(NTOK / 64, 768 / 64);
            bf16_gemm_kernel<64,64,32,32,false><<<grid, 128>>>(
                NTOK, 768, EE, 768, x, wt + (size_t)l * EE * 768, nullptr, qkv);
        }
        attn_kernel<<<BB * HH, 128>>>(qkv, attb);
        // Output projection: [2048,256]@[256,256] + bo
        {
            dim3 grid(NTOK / 64, EE / 64);
            bf16_gemm_kernel<64,64,32,32,false><<<grid, 128>>>(
                NTOK, EE, EE, EE, attb, Wo + (size_t)l * EE * EE, bo + l * EE, y);
        }
        ln_kernel<<<NTOK, EE>>>(x, y, ln1g + l * EE, ln1b + l * EE, x);
        // FFN1: relu([2048,256]@[256,1024] + b1)
        {
            dim3 grid(NTOK / 64, FFN / 64);
            bf16_gemm_kernel<64,64,32,32,true><<<grid, 128>>>(
                NTOK, FFN, EE, FFN, x, W1 + (size_t)l * EE * FFN, b1 + l * FFN, hbuf);
        }
        // FFN2: [2048,1024]@[1024,256] + b2
        {
            dim3 grid(NTOK / 64, EE / 64);
            bf16_gemm_kernel<64,64,32,32,false><<<grid, 128>>>(
                NTOK, EE, FFN, EE, hbuf, W2 + (size_t)l * FFN * EE, b2 + l * EE, y);
        }
        ln_kernel<<<NTOK, EE>>>(x, y, ln2g + l * EE, ln2b + l * EE, x);
    }

    ln_kernel<<<NTOK, EE>>>(x, nullptr, lnfg, lnfb, xf);

    // LM head: [2048,256]@[256,50257] + blm  (padded B, ldb=VPAD; M fastest)
    {
        dim3 grid(NTOK / 128, VPAD / 128);
        bf16_gemm_kernel<128,128,64,32,false><<<grid, 256>>>(
            NTOK, VOCAB, EE, VPAD, xf, wlm, blm, out);
    }
}

// round 13
// speedup vs baseline: 2.8594x; 1.0475x over previous
#include <cuda_runtime.h>
#include <cuda_bf16.h>
#include <math.h>
#include <stdint.h>

// Problem constants
#define VOCAB  50257
#define BB     32
#define TT     64
#define EE     256
#define HH     8
#define DD     32
#define LL     8
#define FFN    1024
#define NTOK   (BB*TT)          // 2048
#define EPSLN  1e-5f
#define VPAD   50304            // 393*128

// ---------------------------------------------------------------------------
// Float scratch
// ---------------------------------------------------------------------------
#define OFF_X    0
#define OFF_QKV  524288
#define OFF_ATT  2097152
#define OFF_H    2621440
#define OFF_PART 4718592                 // 4 x [2048,256] split-K partials
#define OFF_XF   6815744
#define BUF_TOTAL 7340032
__device__ float g_buf[BUF_TOTAL];

// bf16 weight planes (hi/lo)
#define WT_H   0
#define WT_L   1572864
#define WO_H   3145728
#define WO_L   3670016
#define W1_H   4194304
#define W1_L   6291456
#define W2_H   8388608
#define W2_L   10485760
#define WLM_H  12582912
#define WLM_L  25460736
#define WBUF_TOTAL 38338560
__device__ __nv_bfloat16 g_wbuf[WBUF_TOTAL];

// ---------------------------------------------------------------------------
// Helpers
// ---------------------------------------------------------------------------
__device__ __forceinline__ void bsplit(float x, __nv_bfloat16 &h, __nv_bfloat16 &l) {
    h = __float2bfloat16_rn(x);
    l = __float2bfloat16_rn(x - __bfloat162float(h));
}
__device__ __forceinline__ void ldmx4(uint32_t* r, uint32_t saddr) {
    asm volatile("ldmatrix.sync.aligned.m8n8.x4.shared.b16 {%0,%1,%2,%3}, [%4];"
        : "=r"(r[0]), "=r"(r[1]), "=r"(r[2]), "=r"(r[3]) : "r"(saddr));
}
__device__ __forceinline__ void ldmx4t(uint32_t* r, uint32_t saddr) {
    asm volatile("ldmatrix.sync.aligned.m8n8.x4.trans.shared.b16 {%0,%1,%2,%3}, [%4];"
        : "=r"(r[0]), "=r"(r[1]), "=r"(r[2]), "=r"(r[3]) : "r"(saddr));
}
__device__ __forceinline__ void mma_bf16(float* c, const uint32_t* a,
                                         uint32_t b0, uint32_t b1) {
    asm volatile(
        "mma.sync.aligned.m16n8k16.row.col.f32.bf16.bf16.f32 "
        "{%0,%1,%2,%3}, {%4,%5,%6,%7}, {%8,%9}, {%0,%1,%2,%3};"
        : "+f"(c[0]), "+f"(c[1]), "+f"(c[2]), "+f"(c[3])
        : "r"(a[0]), "r"(a[1]), "r"(a[2]), "r"(a[3]), "r"(b0), "r"(b1));
}
__device__ __forceinline__ void cpasync16(uint32_t dst, const void* src) {
    asm volatile("cp.async.cg.shared.global [%0], [%1], 16;" :: "r"(dst), "l"(src));
}
#define CP_COMMIT() asm volatile("cp.async.commit_group;" ::: "memory")
#define CP_WAIT0()  asm volatile("cp.async.wait_group 0;" ::: "memory")

// ---------------------------------------------------------------------------
// Embedding
// ---------------------------------------------------------------------------
__global__ void embed_kernel(const int* __restrict__ ip,
                             const float* __restrict__ tok,
                             const float* __restrict__ pos,
                             float* __restrict__ x) {
    int row = blockIdx.x;
    int c   = threadIdx.x;
    int t   = row & (TT - 1);
    int v   = ip[row];
    x[row * EE + c] = tok[(size_t)v * EE + c] + pos[t * EE + c];
}

// ---------------------------------------------------------------------------
// Weight prep: transpose QKV into [L,E,768] and split to bf16 hi/lo planes
// ---------------------------------------------------------------------------
__global__ void prep_wqkv_split(const float* __restrict__ Wq,
                                const float* __restrict__ Wk,
                                const float* __restrict__ Wv) {
    int idx = blockIdx.x * blockDim.x + threadIdx.x;
    const int total = LL * EE * 768;
    if (idx >= total) return;
    int l = idx / (EE * 768);
    int r = idx % (EE * 768);
    int c = r / 768;
    int j = r % 768;
    int sel = j >> 8;
    int hd  = j & 255;
    int h = hd >> 5, d = hd & 31;
    const float* W = (sel == 0) ? Wq : (sel == 1) ? Wk : Wv;
    float v = W[(((size_t)(l * HH + h) * EE + c) * DD) + d];
    __nv_bfloat16 hi, lo; bsplit(v, hi, lo);
    g_wbuf[WT_H + idx] = hi;
    g_wbuf[WT_L + idx] = lo;
}

// Generic element-wise split
__global__ void split_kernel(const float* __restrict__ src,
                             __nv_bfloat16* __restrict__ hi,
                             __nv_bfloat16* __restrict__ lo, int n) {
    int i = blockIdx.x * blockDim.x + threadIdx.x;
    if (i >= n) return;
    __nv_bfloat16 h, l; bsplit(src[i], h, l);
    hi[i] = h; lo[i] = l;
}

// Wlm [256,VOCAB] -> padded [256,VPAD] hi/lo planes
__global__ void prep_wlm_split(const float* __restrict__ Wlm) {
    size_t idx = (size_t)blockIdx.x * blockDim.x + threadIdx.x;
    const size_t total = (size_t)EE * VPAD;
    if (idx >= total) return;
    int k = (int)(idx / VPAD);
    int n = (int)(idx % VPAD);
    float v = (n < VOCAB) ? Wlm[(size_t)k * VOCAB + n] : 0.f;
    __nv_bfloat16 h, l; bsplit(v, h, l);
    g_wbuf[WLM_H + idx] = h;
    g_wbuf[WLM_L + idx] = l;
}

// ---------------------------------------------------------------------------
// Pipelined 3xBF16 warp-MMA GEMM (cp.async double-buffered, BK=64).
// C[M,N] (+bias,+relu) = A[M,lda-rows] @ B[K,ldb] over k range
// [blockIdx.z*kLen, +kLen). B supplied as pre-split bf16 hi/lo planes.
// Split-K: gridDim.z>1 writes partials at C + z*M*N (bias applied later).
// ---------------------------------------------------------------------------
template<int BM, int BN, int WM, int WN, bool RELU>
__global__ void __launch_bounds__((BM/WM)*(BN/WN)*32)
pgemm_kernel(int M, int N, int lda, int ldb, int kLen,
             const float* __restrict__ A,
             const __nv_bfloat16* __restrict__ Bhi,
             const __nv_bfloat16* __restrict__ Blo,
             const float* __restrict__ bias,
             float* __restrict__ C) {
    constexpr int BK   = 64;
    constexpr int ASTR = BK + 8;
    constexpr int BSTR = BN + 8;
    constexpr int NW   = (BM/WM)*(BN/WN);
    constexpr int NTH  = NW * 32;
    constexpr int MT   = WM / 16;
    constexpr int NT   = WN / 8;
    constexpr int SA   = BM * ASTR;      // bf16 elems per A stage (per plane)
    constexpr int SB   = BK * BSTR;
    constexpr int AREG = BM * 16 / NTH;  // float4 per thread per tile
    constexpr int BCH  = (BK * (BN/8)) / NTH;
    static_assert((BM*16) % NTH == 0 && (BK*(BN/8)) % NTH == 0, "div");
    static_assert(NT % 2 == 0, "NT even");

    extern __shared__ __nv_bfloat16 smem[];
    __nv_bfloat16* Ah = smem;
    __nv_bfloat16* Al = smem + 2*SA;
    __nv_bfloat16* Bh = smem + 4*SA;
    __nv_bfloat16* Bl = smem + 4*SA + 2*SB;

    const int tid  = threadIdx.x;
    const int w    = tid >> 5;
    const int lane = tid & 31;
    const int g    = lane >> 2;
    const int t4   = lane & 3;
    const int wm   = (w / (BN/WN)) * WM;
    const int wn   = (w % (BN/WN)) * WN;
    const int brow = blockIdx.x * BM;
    const int bcol = blockIdx.y * BN;
    const int kOff = blockIdx.z * kLen;
    C += (size_t)blockIdx.z * M * N;
    const bool nedge = (bcol + BN > N);

    const uint32_t ah0 = (uint32_t)__cvta_generic_to_shared(Ah);
    const uint32_t al0 = (uint32_t)__cvta_generic_to_shared(Al);
    const uint32_t bh0 = (uint32_t)__cvta_generic_to_shared(Bh);
    const uint32_t bl0 = (uint32_t)__cvta_generic_to_shared(Bl);

    float acc[MT][NT][4] = {};
    float4 areg[AREG];

    auto loadA = [&](int t) {
        const float* Ab = A + kOff + t * BK;
#pragma unroll
        for (int i = 0; i < AREG; i++) {
            int f = tid + i * NTH, row = f >> 4, kq = (f & 15) << 2;
            areg[i] = *reinterpret_cast<const float4*>(
                Ab + (size_t)(brow + row) * lda + kq);
        }
    };
    auto stsA = [&](int st) {
#pragma unroll
        for (int i = 0; i < AREG; i++) {
            int f = tid + i * NTH, row = f >> 4, kq = (f & 15) << 2;
            __nv_bfloat16 h0,h1,h2,h3,l0,l1,l2,l3;
            bsplit(areg[i].x,h0,l0); bsplit(areg[i].y,h1,l1);
            bsplit(areg[i].z,h2,l2); bsplit(areg[i].w,h3,l3);
            __nv_bfloat162* ph = reinterpret_cast<__nv_bfloat162*>(&Ah[st*SA + row*ASTR + kq]);
            __nv_bfloat162* pl = reinterpret_cast<__nv_bfloat162*>(&Al[st*SA + row*ASTR + kq]);
            ph[0] = __nv_bfloat162(h0,h1); ph[1] = __nv_bfloat162(h2,h3);
            pl[0] = __nv_bfloat162(l0,l1); pl[1] = __nv_bfloat162(l2,l3);
        }
    };
    auto loadB = [&](int t, int st) {
#pragma unroll
        for (int i = 0; i < BCH; i++) {
            int c = tid + i * NTH, kr = c / (BN/8), nc = (c % (BN/8)) * 8;
            size_t goff = (size_t)(kOff + t*BK + kr) * ldb + bcol + nc;
            uint32_t soff = (uint32_t)(st*SB + kr*BSTR + nc) * 2;
            cpasync16(bh0 + soff, Bhi + goff);
            cpasync16(bl0 + soff, Blo + goff);
        }
    };

    const int ntiles = kLen / BK;
    const uint32_t a_ro = (uint32_t)(lane & 15) * (ASTR * 2);
    const uint32_t a_co = (uint32_t)((lane >> 4) << 3) * 2;
    const uint32_t b_ro = (uint32_t)(lane & 15) * (BSTR * 2);
    const uint32_t b_co = (uint32_t)(wn + ((lane >> 4) << 3)) * 2;

    loadA(0); loadB(0, 0); CP_COMMIT();
    stsA(0);
    CP_WAIT0(); __syncthreads();

    int st = 0;
    for (int t = 0; t < ntiles; t++) {
        const bool hn = (t + 1 < ntiles);
        if (hn) { loadA(t + 1); loadB(t + 1, st ^ 1); CP_COMMIT(); }

        const uint32_t ahS = ah0 + (uint32_t)st * SA * 2;
        const uint32_t alS = al0 + (uint32_t)st * SA * 2;
        const uint32_t bhS = bh0 + (uint32_t)st * SB * 2;
        const uint32_t blS = bl0 + (uint32_t)st * SB * 2;
#pragma unroll
        for (int kk = 0; kk < BK; kk += 16) {
            uint32_t afh[MT][4], afl[MT][4];
#pragma unroll
            for (int mt = 0; mt < MT; mt++) {
                uint32_t off = (uint32_t)(wm + mt*16) * (ASTR*2)
                             + a_ro + (uint32_t)kk*2 + a_co;
                ldmx4(afh[mt], ahS + off);
                ldmx4(afl[mt], alS + off);
            }
            uint32_t bfh[NT][2], bfl[NT][2];
#pragma unroll
            for (int p = 0; p < NT/2; p++) {
                uint32_t off = (uint32_t)kk * (BSTR*2) + b_ro
                             + (uint32_t)(p*16)*2 + b_co;
                uint32_t r4[4];
                ldmx4t(r4, bhS + off);
                bfh[2*p][0] = r4[0]; bfh[2*p][1] = r4[1];
                bfh[2*p+1][0] = r4[2]; bfh[2*p+1][1] = r4[3];
                ldmx4t(r4, blS + off);
                bfl[2*p][0] = r4[0]; bfl[2*p][1] = r4[1];
                bfl[2*p+1][0] = r4[2]; bfl[2*p+1][1] = r4[3];
            }
#pragma unroll
            for (int mt = 0; mt < MT; mt++)
#pragma unroll
                for (int nt = 0; nt < NT; nt++) {
                    mma_bf16(acc[mt][nt], afh[mt], bfl[nt][0], bfl[nt][1]);
                    mma_bf16(acc[mt][nt], afl[mt], bfh[nt][0], bfh[nt][1]);
                    mma_bf16(acc[mt][nt], afh[mt], bfh[nt][0], bfh[nt][1]);
                }
        }
        if (hn) { stsA(st ^ 1); CP_WAIT0(); }
        __syncthreads();
        st ^= 1;
    }

    // ---- epilogue ----
    const bool scalar_store = nedge || (N & 1);
#pragma unroll
    for (int mt = 0; mt < MT; mt++) {
        int r0 = brow + wm + mt*16 + g;
        int r1 = r0 + 8;
#pragma unroll
        for (int nt = 0; nt < NT; nt++) {
            int c0 = bcol + wn + nt*8 + 2*t4;
            float v0 = acc[mt][nt][0], v1 = acc[mt][nt][1];
            float v2 = acc[mt][nt][2], v3 = acc[mt][nt][3];
            if (bias) {
                float b0 = (c0   < N) ? bias[c0]   : 0.f;
                float b1 = (c0+1 < N) ? bias[c0+1] : 0.f;
                v0 += b0; v1 += b1; v2 += b0; v3 += b1;
            }
            if (RELU) {
                v0 = fmaxf(v0, 0.f); v1 = fmaxf(v1, 0.f);
                v2 = fmaxf(v2, 0.f); v3 = fmaxf(v3, 0.f);
            }
            if (!scalar_store) {
                float2 p0; p0.x = v0; p0.y = v1;
                float2 p1; p1.x = v2; p1.y = v3;
                *reinterpret_cast<float2*>(C + (size_t)r0 * N + c0) = p0;
                *reinterpret_cast<float2*>(C + (size_t)r1 * N + c0) = p1;
            } else {
                if (c0   < N) { C[(size_t)r0*N + c0]   = v0; C[(size_t)r1*N + c0]   = v2; }
                if (c0+1 < N) { C[(size_t)r0*N + c0+1] = v1; C[(size_t)r1*N + c0+1] = v3; }
            }
        }
    }
}

// ---------------------------------------------------------------------------
// Fused causal attention (online softmax, 2 lanes/query)
// ---------------------------------------------------------------------------
__global__ void attn_kernel(const float* __restrict__ qkv,
                            float* __restrict__ att) {
    __shared__ float ks[TT][DD];
    __shared__ float vs[TT][DD];

    int bh = blockIdx.x;
    int b = bh / HH, h = bh % HH;
    int tid = threadIdx.x;

    const float* base = qkv + (size_t)b * TT * 768 + h * DD;
    for (int i = tid; i < TT * DD; i += 128) {
        int s = i >> 5, d = i & 31;
        ks[s][d] = base[s * 768 + 256 + d];
        vs[s][d] = base[s * 768 + 512 + d];
    }

    const int w    = tid >> 5;
    const int lane = tid & 31;
    const int t     = w * 16 + (lane >> 1);
    const int half  = lane & 1;
    const int dbase = half * 16;
    const float scale = 0.17677669529663687f;

    float q[16];
    const float* qp = base + t * 768 + dbase;
#pragma unroll
    for (int dd = 0; dd < 16; dd++) q[dd] = qp[dd] * scale;

    __syncthreads();

    float m = -1e30f, sum = 0.f;
    float o[16];
#pragma unroll
    for (int dd = 0; dd < 16; dd++) o[dd] = 0.f;

    const int tw = w * 16 + 15;
    for (int s = 0; s <= tw; s++) {
        float part = 0.f;
#pragma unroll
        for (int dd = 0; dd < 16; dd++) part += q[dd] * ks[s][dbase + dd];
        float sc = part + __shfl_xor_sync(0xffffffffu, part, 1);
        if (s <= t) {
            float mn   = fmaxf(m, sc);
            float corr = __expf(m - mn);
            float p    = __expf(sc - mn);
            sum = sum * corr + p;
#pragma unroll
            for (int dd = 0; dd < 16; dd++)
                o[dd] = o[dd] * corr + p * vs[s][dbase + dd];
            m = mn;
        }
    }
    float inv = 1.f / sum;
    float* op = att + (size_t)(b * TT + t) * EE + h * DD + dbase;
#pragma unroll
    for (int dd = 0; dd < 16; dd++) op[dd] = o[dd] * inv;
}

// ---------------------------------------------------------------------------
// Fused: v = x + bias + sum_{s<S} part[s]; out = LN(v; g, b)
// ---------------------------------------------------------------------------
__global__ void reduce_ln_kernel(const float* __restrict__ xin,
                                 const float* __restrict__ part, int S,
                                 const float* __restrict__ bias,
                                 const float* __restrict__ g,
                                 const float* __restrict__ b,
                                 float* __restrict__ out) {
    __shared__ float red1[8];
    __shared__ float red2[8];
    int row = blockIdx.x;
    int c   = threadIdx.x;
    size_t idx = (size_t)row * EE + c;

    float v = xin[idx] + bias[c];
    for (int s = 0; s < S; s++) v += part[(size_t)s * NTOK * EE + idx];

    float sm = v;
#pragma unroll
    for (int o = 16; o > 0; o >>= 1) sm += __shfl_xor_sync(0xffffffffu, sm, o);
    if ((c & 31) == 0) red1[c >> 5] = sm;
    __syncthreads();
    float total = 0.f;
#pragma unroll
    for (int i = 0; i < 8; i++) total += red1[i];
    float mean = total * (1.f / EE);

    float d = v - mean;
    float sq = d * d;
#pragma unroll
    for (int o = 16; o > 0; o >>= 1) sq += __shfl_xor_sync(0xffffffffu, sq, o);
    if ((c & 31) == 0) red2[c >> 5] = sq;
    __syncthreads();
    float tsq = 0.f;
#pragma unroll
    for (int i = 0; i < 8; i++) tsq += red2[i];
    float var = tsq * (1.f / EE);

    out[idx] = d * rsqrtf(var + EPSLN) * g[c] + b[c];
}

// ---------------------------------------------------------------------------
// Plain LayerNorm (final)
// ---------------------------------------------------------------------------
__global__ void ln_kernel(const float* __restrict__ xin,
                          const float* __restrict__ g,
                          const float* __restrict__ b,
                          float* __restrict__ out) {
    __shared__ float red1[8];
    __shared__ float red2[8];
    int row = blockIdx.x;
    int c   = threadIdx.x;
    size_t idx = (size_t)row * EE + c;

    float v = xin[idx];
    float sm = v;
#pragma unroll
    for (int o = 16; o > 0; o >>= 1) sm += __shfl_xor_sync(0xffffffffu, sm, o);
    if ((c & 31) == 0) red1[c >> 5] = sm;
    __syncthreads();
    float total = 0.f;
#pragma unroll
    for (int i = 0; i < 8; i++) total += red1[i];
    float mean = total * (1.f / EE);

    float d = v - mean;
    float sq = d * d;
#pragma unroll
    for (int o = 16; o > 0; o >>= 1) sq += __shfl_xor_sync(0xffffffffu, sq, o);
    if ((c & 31) == 0) red2[c >> 5] = sq;
    __syncthreads();
    float tsq = 0.f;
#pragma unroll
    for (int i = 0; i < 8; i++) tsq += red2[i];
    float var = tsq * (1.f / EE);

    out[idx] = d * rsqrtf(var + EPSLN) * g[c] + b[c];
}

// ---------------------------------------------------------------------------
// Host orchestration
// ---------------------------------------------------------------------------
#define SMEM64  ((4*64*(64+8) + 4*64*(64+8)) * 2)      // 73728 B
#define SMEM128 ((4*128*(64+8) + 4*64*(128+8)) * 2)    // 143360 B

extern "C" void kernel_launch(void* const* d_in, const int* in_sizes, int n_in,
                              void* d_out, int out_size) {
    const int*   ip     = (const int*)  d_in[0];
    const float* tok    = (const float*)d_in[1];
    const float* pos    = (const float*)d_in[2];
    const float* Wq     = (const float*)d_in[3];
    const float* Wk     = (const float*)d_in[4];
    const float* Wv     = (const float*)d_in[5];
    const float* Wo     = (const float*)d_in[6];
    const float* bo     = (const float*)d_in[7];
    const float* ln1g   = (const float*)d_in[8];
    const float* ln1b   = (const float*)d_in[9];
    const float* ln2g   = (const float*)d_in[10];
    const float* ln2b   = (const float*)d_in[11];
    const float* W1     = (const float*)d_in[12];
    const float* b1     = (const float*)d_in[13];
    const float* W2     = (const float*)d_in[14];
    const float* b2     = (const float*)d_in[15];
    const float* lnfg   = (const float*)d_in[16];
    const float* lnfb   = (const float*)d_in[17];
    const float* Wlm    = (const float*)d_in[18];
    const float* blm    = (const float*)d_in[19];
    float*       out    = (float*)d_out;

    cudaFuncSetAttribute(pgemm_kernel<64,64,32,32,false>,
                         cudaFuncAttributeMaxDynamicSharedMemorySize, SMEM64);
    cudaFuncSetAttribute(pgemm_kernel<64,64,32,32,true>,
                         cudaFuncAttributeMaxDynamicSharedMemorySize, SMEM64);
    cudaFuncSetAttribute(pgemm_kernel<128,128,64,32,false>,
                         cudaFuncAttributeMaxDynamicSharedMemorySize, SMEM128);

    float* buf = nullptr;
    cudaGetSymbolAddress((void**)&buf, g_buf);
    __nv_bfloat16* wb = nullptr;
    cudaGetSymbolAddress((void**)&wb, g_wbuf);

    float* x    = buf + OFF_X;
    float* qkv  = buf + OFF_QKV;
    float* attb = buf + OFF_ATT;
    float* hbuf = buf + OFF_H;
    float* part = buf + OFF_PART;
    float* xf   = buf + OFF_XF;

    embed_kernel<<<NTOK, EE>>>(ip, tok, pos, x);

    // Weight prep: split to bf16 hi/lo planes
    {
        int n = LL * EE * 768;
        prep_wqkv_split<<<(n + 255) / 256, 256>>>(Wq, Wk, Wv);
    }
    { int n = LL*EE*EE;  split_kernel<<<(n+255)/256, 256>>>(Wo, wb+WO_H, wb+WO_L, n); }
    { int n = LL*EE*FFN; split_kernel<<<(n+255)/256, 256>>>(W1, wb+W1_H, wb+W1_L, n); }
    { int n = LL*FFN*EE; split_kernel<<<(n+255)/256, 256>>>(W2, wb+W2_H, wb+W2_L, n); }
    {
        size_t n = (size_t)EE * VPAD;
        prep_wlm_split<<<(unsigned)((n + 255) / 256), 256>>>(Wlm);
    }

    for (int l = 0; l < LL; l++) {
        // QKV: [2048,256]@[256,768]
        pgemm_kernel<64,64,32,32,false><<<dim3(32,12,1), 128, SMEM64>>>(
            NTOK, 768, EE, 768, 256, x,
            wb + WT_H + (size_t)l*EE*768, wb + WT_L + (size_t)l*EE*768,
            nullptr, qkv);

        attn_kernel<<<BB * HH, 128>>>(qkv, attb);

        // Wo: [2048,256]@[256,256], split-K2 -> partials
        pgemm_kernel<64,64,32,32,false><<<dim3(32,4,2), 128, SMEM64>>>(
            NTOK, EE, EE, EE, 128, attb,
            wb + WO_H + (size_t)l*EE*EE, wb + WO_L + (size_t)l*EE*EE,
            nullptr, part);
        reduce_ln_kernel<<<NTOK, EE>>>(x, part, 2, bo + l*EE,
                                       ln1g + l*EE, ln1b + l*EE, x);

        // FFN1: relu([2048,256]@[256,1024] + b1)
        pgemm_kernel<64,64,32,32,true><<<dim3(32,16,1), 128, SMEM64>>>(
            NTOK, FFN, EE, FFN, 256, x,
            wb + W1_H + (size_t)l*EE*FFN, wb + W1_L + (size_t)l*EE*FFN,
            b1 + l*FFN, hbuf);

        // FFN2: [2048,1024]@[1024,256], split-K4 -> partials
        pgemm_kernel<64,64,32,32,false><<<dim3(32,4,4), 128, SMEM64>>>(
            NTOK, EE, FFN, EE, 256, hbuf,
            wb + W2_H + (size_t)l*FFN*EE, wb + W2_L + (size_t)l*FFN*EE,
            nullptr, part);
        reduce_ln_kernel<<<NTOK, EE>>>(x, part, 4, b2 + l*EE,
                                       ln2g + l*EE, ln2b + l*EE, x);
    }

    ln_kernel<<<NTOK, EE>>>(x, lnfg, lnfb, xf);

    // LM head: [2048,256]@[256,50257] + blm (padded bf16 planes, ldb=VPAD)
    pgemm_kernel<128,128,64,32,false><<<dim3(16,393,1), 256, SMEM128>>>(
        NTOK, VOCAB, EE, VPAD, 256, xf,
        wb + WLM_H, wb + WLM_L, blm, out);
}

// round 16
// speedup vs baseline: 2.8599x; 1.0002x over previous
#include <cuda_runtime.h>
#include <cuda_bf16.h>
#include <math.h>
#include <stdint.h>

// Problem constants
#define VOCAB  50257
#define BB     32
#define TT     64
#define EE     256
#define HH     8
#define DD     32
#define LL     8
#define FFN    1024
#define NTOK   (BB*TT)          // 2048
#define EPSLN  1e-5f
#define VPAD   50304            // 393*128

// ---------------------------------------------------------------------------
// Float scratch: x, qkv, split-K partials
// ---------------------------------------------------------------------------
#define OFF_X    0
#define OFF_QKV  524288
#define OFF_PART 2097152                 // 4 x [2048,256]
#define BUF_TOTAL 4194304
__device__ float g_buf[BUF_TOTAL];

// bf16 weight planes (hi/lo)
#define WT_H   0
#define WT_L   1572864
#define WO_H   3145728
#define WO_L   3670016
#define W1_H   4194304
#define W1_L   6291456
#define W2_H   8388608
#define W2_L   10485760
#define WLM_H  12582912
#define WLM_L  25460736
#define WBUF_TOTAL 38338560
__device__ __nv_bfloat16 g_wbuf[WBUF_TOTAL];

// bf16 activation planes (hi/lo)
#define AX_H   0
#define AX_L   524288
#define AT_H   1048576
#define AT_L   1572864
#define AH_H   2097152
#define AH_L   4194304
#define AF_H   6291456
#define AF_L   6815744
#define ABUF_TOTAL 7340032
__device__ __nv_bfloat16 g_abuf[ABUF_TOTAL];

// ---------------------------------------------------------------------------
// Helpers
// ---------------------------------------------------------------------------
__device__ __forceinline__ void bsplit(float x, __nv_bfloat16 &h, __nv_bfloat16 &l) {
    h = __float2bfloat16_rn(x);
    l = __float2bfloat16_rn(x - __bfloat162float(h));
}
__device__ __forceinline__ void ldmx4(uint32_t* r, uint32_t saddr) {
    asm volatile("ldmatrix.sync.aligned.m8n8.x4.shared.b16 {%0,%1,%2,%3}, [%4];"
        : "=r"(r[0]), "=r"(r[1]), "=r"(r[2]), "=r"(r[3]) : "r"(saddr));
}
__device__ __forceinline__ void ldmx4t(uint32_t* r, uint32_t saddr) {
    asm volatile("ldmatrix.sync.aligned.m8n8.x4.trans.shared.b16 {%0,%1,%2,%3}, [%4];"
        : "=r"(r[0]), "=r"(r[1]), "=r"(r[2]), "=r"(r[3]) : "r"(saddr));
}
__device__ __forceinline__ void mma_bf16(float* c, const uint32_t* a,
                                         uint32_t b0, uint32_t b1) {
    asm volatile(
        "mma.sync.aligned.m16n8k16.row.col.f32.bf16.bf16.f32 "
        "{%0,%1,%2,%3}, {%4,%5,%6,%7}, {%8,%9}, {%0,%1,%2,%3};"
        : "+f"(c[0]), "+f"(c[1]), "+f"(c[2]), "+f"(c[3])
        : "r"(a[0]), "r"(a[1]), "r"(a[2]), "r"(a[3]), "r"(b0), "r"(b1));
}
__device__ __forceinline__ void cpasync16(uint32_t dst, const void* src) {
    asm volatile("cp.async.cg.shared.global [%0], [%1], 16;" :: "r"(dst), "l"(src));
}
#define CP_COMMIT() asm volatile("cp.async.commit_group;" ::: "memory")
#define CP_WAIT0()  asm volatile("cp.async.wait_group 0;" ::: "memory")
#define CP_WAIT1()  asm volatile("cp.async.wait_group 1;" ::: "memory")

// ---------------------------------------------------------------------------
// Embedding: x fp32 + bf16 hi/lo planes
// ---------------------------------------------------------------------------
__global__ void embed_kernel(const int* __restrict__ ip,
                             const float* __restrict__ tok,
                             const float* __restrict__ pos,
                             float* __restrict__ x,
                             __nv_bfloat16* __restrict__ xh,
                             __nv_bfloat16* __restrict__ xl) {
    int row = blockIdx.x;
    int c   = threadIdx.x;
    int t   = row & (TT - 1);
    int v   = ip[row];
    float val = tok[(size_t)v * EE + c] + pos[t * EE + c];
    size_t idx = (size_t)row * EE + c;
    x[idx] = val;
    __nv_bfloat16 h, l; bsplit(val, h, l);
    xh[idx] = h; xl[idx] = l;
}

// ---------------------------------------------------------------------------
// Weight prep
// ---------------------------------------------------------------------------
__global__ void prep_wqkv_split(const float* __restrict__ Wq,
                                const float* __restrict__ Wk,
                                const float* __restrict__ Wv) {
    int idx = blockIdx.x * blockDim.x + threadIdx.x;
    const int total = LL * EE * 768;
    if (idx >= total) return;
    int l = idx / (EE * 768);
    int r = idx % (EE * 768);
    int c = r / 768;
    int j = r % 768;
    int sel = j >> 8;
    int hd  = j & 255;
    int h = hd >> 5, d = hd & 31;
    const float* W = (sel == 0) ? Wq : (sel == 1) ? Wk : Wv;
    float v = W[(((size_t)(l * HH + h) * EE + c) * DD) + d];
    __nv_bfloat16 hi, lo; bsplit(v, hi, lo);
    g_wbuf[WT_H + idx] = hi;
    g_wbuf[WT_L + idx] = lo;
}

__global__ void split_kernel(const float* __restrict__ src,
                             __nv_bfloat16* __restrict__ hi,
                             __nv_bfloat16* __restrict__ lo, int n) {
    int i = blockIdx.x * blockDim.x + threadIdx.x;
    if (i >= n) return;
    __nv_bfloat16 h, l; bsplit(src[i], h, l);
    hi[i] = h; lo[i] = l;
}

__global__ void prep_wlm_split(const float* __restrict__ Wlm) {
    size_t idx = (size_t)blockIdx.x * blockDim.x + threadIdx.x;
    const size_t total = (size_t)EE * VPAD;
    if (idx >= total) return;
    int k = (int)(idx / VPAD);
    int n = (int)(idx % VPAD);
    float v = (n < VOCAB) ? Wlm[(size_t)k * VOCAB + n] : 0.f;
    __nv_bfloat16 h, l; bsplit(v, h, l);
    g_wbuf[WLM_H + idx] = h;
    g_wbuf[WLM_L + idx] = l;
}

// ---------------------------------------------------------------------------
// Fully-async 3-stage 3xBF16 warp-MMA GEMM.
// A, B both pre-split bf16 hi/lo planes, row-major with strides lda/ldb.
// k range [blockIdx.z*kLen, +kLen); split-K partials for OUTM==0 at C+z*M*N.
// OUTM: 0 = fp32 C (+bias if given, +relu), 1 = bf16 hi/lo planes out.
// ---------------------------------------------------------------------------
template<int BM, int BN, int WM, int WN, bool RELU, int OUTM>
__global__ void __launch_bounds__((BM/WM)*(BN/WN)*32)
pgemm_kernel(int M, int N, int lda, int ldb, int kLen,
             const __nv_bfloat16* __restrict__ Ahi,
             const __nv_bfloat16* __restrict__ Alo,
             const __nv_bfloat16* __restrict__ Bhi,
             const __nv_bfloat16* __restrict__ Blo,
             const float* __restrict__ bias,
             float* __restrict__ C,
             __nv_bfloat16* __restrict__ Chi,
             __nv_bfloat16* __restrict__ Clo) {
    constexpr int BK   = 64;
    constexpr int ST   = 3;
    constexpr int ASTR = BK + 8;
    constexpr int BSTR = BN + 8;
    constexpr int NW   = (BM/WM)*(BN/WN);
    constexpr int NTH  = NW * 32;
    constexpr int MT   = WM / 16;
    constexpr int NT   = WN / 8;
    constexpr int SA   = BM * ASTR;
    constexpr int SB   = BK * BSTR;
    constexpr int STG  = 2*SA + 2*SB;         // elems per stage
    constexpr int ACH  = BM * (BK/8) / NTH;   // 16B chunks per thread (per plane)
    constexpr int BCH  = BK * (BN/8) / NTH;
    static_assert((BM*(BK/8)) % NTH == 0 && (BK*(BN/8)) % NTH == 0, "div");
    static_assert(NT % 2 == 0, "NT even");

    extern __shared__ __nv_bfloat16 smem[];

    const int tid  = threadIdx.x;
    const int w    = tid >> 5;
    const int lane = tid & 31;
    const int g    = lane >> 2;
    const int t4   = lane & 3;
    const int wm   = (w / (BN/WN)) * WM;
    const int wn   = (w % (BN/WN)) * WN;
    const int brow = blockIdx.x * BM;
    const int bcol = blockIdx.y * BN;
    const int kOff = blockIdx.z * kLen;
    if (OUTM == 0) C += (size_t)blockIdx.z * M * N;
    const bool nedge = (bcol + BN > N);

    const uint32_t sm0 = (uint32_t)__cvta_generic_to_shared(smem);

    float acc[MT][NT][4] = {};

    auto loadTile = [&](int t, int stg) {
        const uint32_t sbase = sm0 + (uint32_t)(stg * STG) * 2;
#pragma unroll
        for (int i = 0; i < ACH; i++) {
            int c = tid + i * NTH;
            int row = c / (BK/8);
            int kc  = (c % (BK/8)) * 8;
            size_t go = (size_t)(brow + row) * lda + kOff + t*BK + kc;
            uint32_t d = sbase + (uint32_t)(row*ASTR + kc) * 2;
            cpasync16(d, Ahi + go);
            cpasync16(d + (uint32_t)SA*2, Alo + go);
        }
#pragma unroll
        for (int i = 0; i < BCH; i++) {
            int c = tid + i * NTH;
            int kr = c / (BN/8);
            int nc = (c % (BN/8)) * 8;
            size_t go = (size_t)(kOff + t*BK + kr) * ldb + bcol + nc;
            uint32_t d = sbase + (uint32_t)(2*SA + kr*BSTR + nc) * 2;
            cpasync16(d, Bhi + go);
            cpasync16(d + (uint32_t)SB*2, Blo + go);
        }
    };

    const int ntiles = kLen / BK;
    const uint32_t a_ro = (uint32_t)(lane & 15) * (ASTR * 2);
    const uint32_t a_co = (uint32_t)((lane >> 4) << 3) * 2;
    const uint32_t b_ro = (uint32_t)(lane & 15) * (BSTR * 2);
    const uint32_t b_co = (uint32_t)(wn + ((lane >> 4) << 3)) * 2;

    const int pre = (ntiles < ST-1) ? ntiles : ST-1;
    for (int s = 0; s < pre; s++) { loadTile(s, s); CP_COMMIT(); }

    int st = 0;
    for (int t = 0; t < ntiles; t++) {
        if (t < ntiles - 1) CP_WAIT1(); else CP_WAIT0();
        __syncthreads();

        const uint32_t sbase = sm0 + (uint32_t)(st * STG) * 2;
#pragma unroll
        for (int kk = 0; kk < BK; kk += 16) {
            uint32_t afh[MT][4], afl[MT][4];
#pragma unroll
            for (int mt = 0; mt < MT; mt++) {
                uint32_t off = sbase + (uint32_t)(wm + mt*16) * (ASTR*2)
                             + a_ro + (uint32_t)kk*2 + a_co;
                ldmx4(afh[mt], off);
                ldmx4(afl[mt], off + (uint32_t)SA*2);
            }
            uint32_t bfh[NT][2], bfl[NT][2];
#pragma unroll
            for (int p = 0; p < NT/2; p++) {
                uint32_t off = sbase + (uint32_t)(2*SA)*2 + (uint32_t)kk * (BSTR*2)
                             + b_ro + (uint32_t)(p*16)*2 + b_co;
                uint32_t r4[4];
                ldmx4t(r4, off);
                bfh[2*p][0] = r4[0]; bfh[2*p][1] = r4[1];
                bfh[2*p+1][0] = r4[2]; bfh[2*p+1][1] = r4[3];
                ldmx4t(r4, off + (uint32_t)SB*2);
                bfl[2*p][0] = r4[0]; bfl[2*p][1] = r4[1];
                bfl[2*p+1][0] = r4[2]; bfl[2*p+1][1] = r4[3];
            }
#pragma unroll
            for (int mt = 0; mt < MT; mt++)
#pragma unroll
                for (int nt = 0; nt < NT; nt++) {
                    mma_bf16(acc[mt][nt], afh[mt], bfl[nt][0], bfl[nt][1]);
                    mma_bf16(acc[mt][nt], afl[mt], bfh[nt][0], bfh[nt][1]);
                    mma_bf16(acc[mt][nt], afh[mt], bfh[nt][0], bfh[nt][1]);
                }
        }
        __syncthreads();
        if (t + ST - 1 < ntiles) {
            loadTile(t + ST - 1, (st + ST - 1) % ST);
            CP_COMMIT();
        }
        st = (st == ST-1) ? 0 : st + 1;
    }

    // ---- epilogue ----
#pragma unroll
    for (int mt = 0; mt < MT; mt++) {
        int r0 = brow + wm + mt*16 + g;
        int r1 = r0 + 8;
#pragma unroll
        for (int nt = 0; nt < NT; nt++) {
            int c0 = bcol + wn + nt*8 + 2*t4;
            float v0 = acc[mt][nt][0], v1 = acc[mt][nt][1];
            float v2 = acc[mt][nt][2], v3 = acc[mt][nt][3];
            if (bias) {
                float b0 = (c0   < N) ? bias[c0]   : 0.f;
                float b1 = (c0+1 < N) ? bias[c0+1] : 0.f;
                v0 += b0; v1 += b1; v2 += b0; v3 += b1;
            }
            if (RELU) {
                v0 = fmaxf(v0, 0.f); v1 = fmaxf(v1, 0.f);
                v2 = fmaxf(v2, 0.f); v3 = fmaxf(v3, 0.f);
            }
            if (OUTM == 1) {
                __nv_bfloat16 h0,l0,h1,l1;
                bsplit(v0,h0,l0); bsplit(v1,h1,l1);
                *reinterpret_cast<__nv_bfloat162*>(Chi + (size_t)r0*N + c0) = __nv_bfloat162(h0,h1);
                *reinterpret_cast<__nv_bfloat162*>(Clo + (size_t)r0*N + c0) = __nv_bfloat162(l0,l1);
                bsplit(v2,h0,l0); bsplit(v3,h1,l1);
                *reinterpret_cast<__nv_bfloat162*>(Chi + (size_t)r1*N + c0) = __nv_bfloat162(h0,h1);
                *reinterpret_cast<__nv_bfloat162*>(Clo + (size_t)r1*N + c0) = __nv_bfloat162(l0,l1);
            } else {
                const bool scalar_store = nedge || (N & 1);
                if (!scalar_store) {
                    float2 p0; p0.x = v0; p0.y = v1;
                    float2 p1; p1.x = v2; p1.y = v3;
                    *reinterpret_cast<float2*>(C + (size_t)r0 * N + c0) = p0;
                    *reinterpret_cast<float2*>(C + (size_t)r1 * N + c0) = p1;
                } else {
                    if (c0   < N) { C[(size_t)r0*N + c0]   = v0; C[(size_t)r1*N + c0]   = v2; }
                    if (c0+1 < N) { C[(size_t)r0*N + c0+1] = v1; C[(size_t)r1*N + c0+1] = v3; }
                }
            }
        }
    }
}

// ---------------------------------------------------------------------------
// Fused causal attention -> bf16 hi/lo planes
// ---------------------------------------------------------------------------
__global__ void attn_kernel(const float* __restrict__ qkv,
                            __nv_bfloat16* __restrict__ atth,
                            __nv_bfloat16* __restrict__ attl) {
    __shared__ float ks[TT][DD];
    __shared__ float vs[TT][DD];

    int bh = blockIdx.x;
    int b = bh / HH, h = bh % HH;
    int tid = threadIdx.x;

    const float* base = qkv + (size_t)b * TT * 768 + h * DD;
    for (int i = tid; i < TT * DD; i += 128) {
        int s = i >> 5, d = i & 31;
        ks[s][d] = base[s * 768 + 256 + d];
        vs[s][d] = base[s * 768 + 512 + d];
    }

    const int w    = tid >> 5;
    const int lane = tid & 31;
    const int t     = w * 16 + (lane >> 1);
    const int half  = lane & 1;
    const int dbase = half * 16;
    const float scale = 0.17677669529663687f;

    float q[16];
    const float* qp = base + t * 768 + dbase;
#pragma unroll
    for (int dd = 0; dd < 16; dd++) q[dd] = qp[dd] * scale;

    __syncthreads();

    float m = -1e30f, sum = 0.f;
    float o[16];
#pragma unroll
    for (int dd = 0; dd < 16; dd++) o[dd] = 0.f;

    const int tw = w * 16 + 15;
    for (int s = 0; s <= tw; s++) {
        float part = 0.f;
#pragma unroll
        for (int dd = 0; dd < 16; dd++) part += q[dd] * ks[s][dbase + dd];
        float sc = part + __shfl_xor_sync(0xffffffffu, part, 1);
        if (s <= t) {
            float mn   = fmaxf(m, sc);
            float corr = __expf(m - mn);
            float p    = __expf(sc - mn);
            sum = sum * corr + p;
#pragma unroll
            for (int dd = 0; dd < 16; dd++)
                o[dd] = o[dd] * corr + p * vs[s][dbase + dd];
            m = mn;
        }
    }
    float inv = 1.f / sum;
    size_t op = (size_t)(b * TT + t) * EE + h * DD + dbase;
#pragma unroll
    for (int dd = 0; dd < 16; dd++) {
        __nv_bfloat16 hh, ll; bsplit(o[dd] * inv, hh, ll);
        atth[op + dd] = hh; attl[op + dd] = ll;
    }
}

// ---------------------------------------------------------------------------
// Fused: v = x + bias + sum part[s]; out fp32 + bf16 hi/lo of LN(v)
// ---------------------------------------------------------------------------
__global__ void reduce_ln_kernel(const float* __restrict__ xin,
                                 const float* __restrict__ part, int S,
                                 const float* __restrict__ bias,
                                 const float* __restrict__ g,
                                 const float* __restrict__ b,
                                 float* __restrict__ outF,
                                 __nv_bfloat16* __restrict__ outH,
                                 __nv_bfloat16* __restrict__ outL) {
    __shared__ float red1[8];
    __shared__ float red2[8];
    int row = blockIdx.x;
    int c   = threadIdx.x;
    size_t idx = (size_t)row * EE + c;

    float v = xin[idx] + bias[c];
    for (int s = 0; s < S; s++) v += part[(size_t)s * NTOK * EE + idx];

    float sm = v;
#pragma unroll
    for (int o = 16; o > 0; o >>= 1) sm += __shfl_xor_sync(0xffffffffu, sm, o);
    if ((c & 31) == 0) red1[c >> 5] = sm;
    __syncthreads();
    float total = 0.f;
#pragma unroll
    for (int i = 0; i < 8; i++) total += red1[i];
    float mean = total * (1.f / EE);

    float d = v - mean;
    float sq = d * d;
#pragma unroll
    for (int o = 16; o > 0; o >>= 1) sq += __shfl_xor_sync(0xffffffffu, sq, o);
    if ((c & 31) == 0) red2[c >> 5] = sq;
    __syncthreads();
    float tsq = 0.f;
#pragma unroll
    for (int i = 0; i < 8; i++) tsq += red2[i];
    float var = tsq * (1.f / EE);

    float r = d * rsqrtf(var + EPSLN) * g[c] + b[c];
    outF[idx] = r;
    __nv_bfloat16 hh, ll; bsplit(r, hh, ll);
    outH[idx] = hh; outL[idx] = ll;
}

// ---------------------------------------------------------------------------
// Final LayerNorm -> bf16 hi/lo planes only
// ---------------------------------------------------------------------------
__global__ void ln_final_kernel(const float* __restrict__ xin,
                                const float* __restrict__ g,
                                const float* __restrict__ b,
                                __nv_bfloat16* __restrict__ outH,
                                __nv_bfloat16* __restrict__ outL) {
    __shared__ float red1[8];
    __shared__ float red2[8];
    int row = blockIdx.x;
    int c   = threadIdx.x;
    size_t idx = (size_t)row * EE + c;

    float v = xin[idx];
    float sm = v;
#pragma unroll
    for (int o = 16; o > 0; o >>= 1) sm += __shfl_xor_sync(0xffffffffu, sm, o);
    if ((c & 31) == 0) red1[c >> 5] = sm;
    __syncthreads();
    float total = 0.f;
#pragma unroll
    for (int i = 0; i < 8; i++) total += red1[i];
    float mean = total * (1.f / EE);

    float d = v - mean;
    float sq = d * d;
#pragma unroll
    for (int o = 16; o > 0; o >>= 1) sq += __shfl_xor_sync(0xffffffffu, sq, o);
    if ((c & 31) == 0) red2[c >> 5] = sq;
    __syncthreads();
    float tsq = 0.f;
#pragma unroll
    for (int i = 0; i < 8; i++) tsq += red2[i];
    float var = tsq * (1.f / EE);

    float r = d * rsqrtf(var + EPSLN) * g[c] + b[c];
    __nv_bfloat16 hh, ll; bsplit(r, hh, ll);
    outH[idx] = hh; outL[idx] = ll;
}

// ---------------------------------------------------------------------------
// Host orchestration
// ---------------------------------------------------------------------------
#define SMEM64  110592
#define SMEMLM  215040

extern "C" void kernel_launch(void* const* d_in, const int* in_sizes, int n_in,
                              void* d_out, int out_size) {
    const int*   ip     = (const int*)  d_in[0];
    const float* tok    = (const float*)d_in[1];
    const float* pos    = (const float*)d_in[2];
    const float* Wq     = (const float*)d_in[3];
    const float* Wk     = (const float*)d_in[4];
    const float* Wv     = (const float*)d_in[5];
    const float* Wo     = (const float*)d_in[6];
    const float* bo     = (const float*)d_in[7];
    const float* ln1g   = (const float*)d_in[8];
    const float* ln1b   = (const float*)d_in[9];
    const float* ln2g   = (const float*)d_in[10];
    const float* ln2b   = (const float*)d_in[11];
    const float* W1     = (const float*)d_in[12];
    const float* b1     = (const float*)d_in[13];
    const float* W2     = (const float*)d_in[14];
    const float* b2     = (const float*)d_in[15];
    const float* lnfg   = (const float*)d_in[16];
    const float* lnfb   = (const float*)d_in[17];
    const float* Wlm    = (const float*)d_in[18];
    const float* blm    = (const float*)d_in[19];
    float*       out    = (float*)d_out;

    cudaFuncSetAttribute(pgemm_kernel<64,64,32,32,false,0>,
                         cudaFuncAttributeMaxDynamicSharedMemorySize, SMEM64);
    cudaFuncSetAttribute(pgemm_kernel<64,64,32,32,true,1>,
                         cudaFuncAttributeMaxDynamicSharedMemorySize, SMEM64);
    cudaFuncSetAttribute(pgemm_kernel<128,128,64,32,false,0>,
                         cudaFuncAttributeMaxDynamicSharedMemorySize, SMEMLM);

    float* buf = nullptr;
    cudaGetSymbolAddress((void**)&buf, g_buf);
    __nv_bfloat16* wb = nullptr;
    cudaGetSymbolAddress((void**)&wb, g_wbuf);
    __nv_bfloat16* ab = nullptr;
    cudaGetSymbolAddress((void**)&ab, g_abuf);

    float* x    = buf + OFF_X;
    float* qkv  = buf + OFF_QKV;
    float* part = buf + OFF_PART;

    embed_kernel<<<NTOK, EE>>>(ip, tok, pos, x, ab + AX_H, ab + AX_L);

    {
        int n = LL * EE * 768;
        prep_wqkv_split<<<(n + 255) / 256, 256>>>(Wq, Wk, Wv);
    }
    { int n = LL*EE*EE;  split_kernel<<<(n+255)/256, 256>>>(Wo, wb+WO_H, wb+WO_L, n); }
    { int n = LL*EE*FFN; split_kernel<<<(n+255)/256, 256>>>(W1, wb+W1_H, wb+W1_L, n); }
    { int n = LL*FFN*EE; split_kernel<<<(n+255)/256, 256>>>(W2, wb+W2_H, wb+W2_L, n); }
    {
        size_t n = (size_t)EE * VPAD;
        prep_wlm_split<<<(unsigned)((n + 255) / 256), 256>>>(Wlm);
    }

    for (int l = 0; l < LL; l++) {
        // QKV: [2048,256]@[256,768] -> fp32
        pgemm_kernel<64,64,32,32,false,0><<<dim3(32,12,1), 128, SMEM64>>>(
            NTOK, 768, EE, 768, 256,
            ab + AX_H, ab + AX_L,
            wb + WT_H + (size_t)l*EE*768, wb + WT_L + (size_t)l*EE*768,
            nullptr, qkv, nullptr, nullptr);

        attn_kernel<<<BB * HH, 128>>>(qkv, ab + AT_H, ab + AT_L);

        // Wo: split-K2 -> fp32 partials
        pgemm_kernel<64,64,32,32,false,0><<<dim3(32,4,2), 128, SMEM64>>>(
            NTOK, EE, EE, EE, 128,
            ab + AT_H, ab + AT_L,
            wb + WO_H + (size_t)l*EE*EE, wb + WO_L + (size_t)l*EE*EE,
            nullptr, part, nullptr, nullptr);
        reduce_ln_kernel<<<NTOK, EE>>>(x, part, 2, bo + l*EE,
                                       ln1g + l*EE, ln1b + l*EE,
                                       x, ab + AX_H, ab + AX_L);

        // FFN1: relu -> bf16 hi/lo planes
        pgemm_kernel<64,64,32,32,true,1><<<dim3(32,16,1), 128, SMEM64>>>(
            NTOK, FFN, EE, FFN, 256,
            ab + AX_H, ab + AX_L,
            wb + W1_H + (size_t)l*EE*FFN, wb + W1_L + (size_t)l*EE*FFN,
            b1 + l*FFN, nullptr, ab + AH_H, ab + AH_L);

        // FFN2: split-K4 -> fp32 partials
        pgemm_kernel<64,64,32,32,false,0><<<dim3(32,4,4), 128, SMEM64>>>(
            NTOK, EE, FFN, EE, 256,
            ab + AH_H, ab + AH_L,
            wb + W2_H + (size_t)l*FFN*EE, wb + W2_L + (size_t)l*FFN*EE,
            nullptr, part, nullptr, nullptr);
        reduce_ln_kernel<<<NTOK, EE>>>(x, part, 4, b2 + l*EE,
                                       ln2g + l*EE, ln2b + l*EE,
                                       x, ab + AX_H, ab + AX_L);
    }

    ln_final_kernel<<<NTOK, EE>>>(x, lnfg, lnfb, ab + AF_H, ab + AF_L);

    // LM head: [2048,256]@[256,50257] + blm
    pgemm_kernel<128,128,64,32,false,0><<<dim3(16,393,1), 256, SMEMLM>>>(
        NTOK, VOCAB, EE, VPAD, 256,
        ab + AF_H, ab + AF_L,
        wb + WLM_H, wb + WLM_L,
        blm, out, nullptr, nullptr);
}

// round 17
// speedup vs baseline: 3.0403x; 1.0631x over previous
#include <cuda_runtime.h>
#include <cuda_bf16.h>
#include <cuda_fp16.h>
#include <math.h>
#include <stdint.h>

// Problem constants
#define VOCAB  50257
#define BB     32
#define TT     64
#define EE     256
#define HH     8
#define DD     32
#define LL     8
#define FFN    1024
#define NTOK   (BB*TT)          // 2048
#define EPSLN  1e-5f
#define VPAD   50304            // 393*128

// ---------------------------------------------------------------------------
// Float scratch: x, qkv, split-K partials
// ---------------------------------------------------------------------------
#define OFF_X    0
#define OFF_QKV  524288
#define OFF_PART 2097152                 // 4 x [2048,256]
#define BUF_TOTAL 4194304
__device__ float g_buf[BUF_TOTAL];

// bf16 weight planes (hi/lo) — layer GEMMs
#define WT_H   0
#define WT_L   1572864
#define WO_H   3145728
#define WO_L   3670016
#define W1_H   4194304
#define W1_L   6291456
#define W2_H   8388608
#define W2_L   10485760
#define WBUF_TOTAL 12582912
__device__ __nv_bfloat16 g_wbuf[WBUF_TOTAL];

// bf16 activation planes (hi/lo)
#define AX_H   0
#define AX_L   524288
#define AT_H   1048576
#define AT_L   1572864
#define AH_H   2097152
#define AH_L   4194304
#define ABUF_TOTAL 6291456
__device__ __nv_bfloat16 g_abuf[ABUF_TOTAL];

// fp16 planes for LM head: xf hi/lo + Wlm single plane (padded)
#define XF_H   0
#define XF_L   524288
#define WLMH   1048576
#define HBUF_TOTAL (1048576 + EE*VPAD)
__device__ __half g_hbuf[HBUF_TOTAL];

// ---------------------------------------------------------------------------
// Helpers
// ---------------------------------------------------------------------------
__device__ __forceinline__ void bsplit(float x, __nv_bfloat16 &h, __nv_bfloat16 &l) {
    h = __float2bfloat16_rn(x);
    l = __float2bfloat16_rn(x - __bfloat162float(h));
}
__device__ __forceinline__ void hsplit(float x, __half &h, __half &l) {
    h = __float2half_rn(x);
    l = __float2half_rn(x - __half2float(h));
}
__device__ __forceinline__ void ldmx4(uint32_t* r, uint32_t saddr) {
    asm volatile("ldmatrix.sync.aligned.m8n8.x4.shared.b16 {%0,%1,%2,%3}, [%4];"
        : "=r"(r[0]), "=r"(r[1]), "=r"(r[2]), "=r"(r[3]) : "r"(saddr));
}
__device__ __forceinline__ void ldmx4t(uint32_t* r, uint32_t saddr) {
    asm volatile("ldmatrix.sync.aligned.m8n8.x4.trans.shared.b16 {%0,%1,%2,%3}, [%4];"
        : "=r"(r[0]), "=r"(r[1]), "=r"(r[2]), "=r"(r[3]) : "r"(saddr));
}
__device__ __forceinline__ void mma_bf16(float* c, const uint32_t* a,
                                         uint32_t b0, uint32_t b1) {
    asm volatile(
        "mma.sync.aligned.m16n8k16.row.col.f32.bf16.bf16.f32 "
        "{%0,%1,%2,%3}, {%4,%5,%6,%7}, {%8,%9}, {%0,%1,%2,%3};"
        : "+f"(c[0]), "+f"(c[1]), "+f"(c[2]), "+f"(c[3])
        : "r"(a[0]), "r"(a[1]), "r"(a[2]), "r"(a[3]), "r"(b0), "r"(b1));
}
__device__ __forceinline__ void mma_f16(float* c, const uint32_t* a,
                                        uint32_t b0, uint32_t b1) {
    asm volatile(
        "mma.sync.aligned.m16n8k16.row.col.f32.f16.f16.f32 "
        "{%0,%1,%2,%3}, {%4,%5,%6,%7}, {%8,%9}, {%0,%1,%2,%3};"
        : "+f"(c[0]), "+f"(c[1]), "+f"(c[2]), "+f"(c[3])
        : "r"(a[0]), "r"(a[1]), "r"(a[2]), "r"(a[3]), "r"(b0), "r"(b1));
}
__device__ __forceinline__ void cpasync16(uint32_t dst, const void* src) {
    asm volatile("cp.async.cg.shared.global [%0], [%1], 16;" :: "r"(dst), "l"(src));
}
#define CP_COMMIT() asm volatile("cp.async.commit_group;" ::: "memory")
#define CP_WAIT0()  asm volatile("cp.async.wait_group 0;" ::: "memory")
#define CP_WAIT1()  asm volatile("cp.async.wait_group 1;" ::: "memory")

// ---------------------------------------------------------------------------
// Embedding: x fp32 + bf16 hi/lo planes
// ---------------------------------------------------------------------------
__global__ void embed_kernel(const int* __restrict__ ip,
                             const float* __restrict__ tok,
                             const float* __restrict__ pos,
                             float* __restrict__ x,
                             __nv_bfloat16* __restrict__ xh,
                             __nv_bfloat16* __restrict__ xl) {
    int row = blockIdx.x;
    int c   = threadIdx.x;
    int t   = row & (TT - 1);
    int v   = ip[row];
    float val = tok[(size_t)v * EE + c] + pos[t * EE + c];
    size_t idx = (size_t)row * EE + c;
    x[idx] = val;
    __nv_bfloat16 h, l; bsplit(val, h, l);
    xh[idx] = h; xl[idx] = l;
}

// ---------------------------------------------------------------------------
// Weight prep
// ---------------------------------------------------------------------------
__global__ void prep_wqkv_split(const float* __restrict__ Wq,
                                const float* __restrict__ Wk,
                                const float* __restrict__ Wv) {
    int idx = blockIdx.x * blockDim.x + threadIdx.x;
    const int total = LL * EE * 768;
    if (idx >= total) return;
    int l = idx / (EE * 768);
    int r = idx % (EE * 768);
    int c = r / 768;
    int j = r % 768;
    int sel = j >> 8;
    int hd  = j & 255;
    int h = hd >> 5, d = hd & 31;
    const float* W = (sel == 0) ? Wq : (sel == 1) ? Wk : Wv;
    float v = W[(((size_t)(l * HH + h) * EE + c) * DD) + d];
    __nv_bfloat16 hi, lo; bsplit(v, hi, lo);
    g_wbuf[WT_H + idx] = hi;
    g_wbuf[WT_L + idx] = lo;
}

__global__ void split_kernel(const float* __restrict__ src,
                             __nv_bfloat16* __restrict__ hi,
                             __nv_bfloat16* __restrict__ lo, int n) {
    int i = blockIdx.x * blockDim.x + threadIdx.x;
    if (i >= n) return;
    __nv_bfloat16 h, l; bsplit(src[i], h, l);
    hi[i] = h; lo[i] = l;
}

// Wlm [256,VOCAB] -> padded fp16 single plane [256,VPAD]
__global__ void prep_wlm_h(const float* __restrict__ Wlm) {
    size_t idx = (size_t)blockIdx.x * blockDim.x + threadIdx.x;
    const size_t total = (size_t)EE * VPAD;
    if (idx >= total) return;
    int k = (int)(idx / VPAD);
    int n = (int)(idx % VPAD);
    float v = (n < VOCAB) ? Wlm[(size_t)k * VOCAB + n] : 0.f;
    g_hbuf[WLMH + idx] = __float2half_rn(v);
}

// ---------------------------------------------------------------------------
// 3-stage async 3xBF16 warp-MMA GEMM (layer GEMMs).
// ---------------------------------------------------------------------------
template<int BM, int BN, int WM, int WN, bool RELU, int OUTM>
__global__ void __launch_bounds__((BM/WM)*(BN/WN)*32)
pgemm_kernel(int M, int N, int lda, int ldb, int kLen,
             const __nv_bfloat16* __restrict__ Ahi,
             const __nv_bfloat16* __restrict__ Alo,
             const __nv_bfloat16* __restrict__ Bhi,
             const __nv_bfloat16* __restrict__ Blo,
             const float* __restrict__ bias,
             float* __restrict__ C,
             __nv_bfloat16* __restrict__ Chi,
             __nv_bfloat16* __restrict__ Clo) {
    constexpr int BK   = 64;
    constexpr int ST   = 3;
    constexpr int ASTR = BK + 8;
    constexpr int BSTR = BN + 8;
    constexpr int NW   = (BM/WM)*(BN/WN);
    constexpr int NTH  = NW * 32;
    constexpr int MT   = WM / 16;
    constexpr int NT   = WN / 8;
    constexpr int SA   = BM * ASTR;
    constexpr int SB   = BK * BSTR;
    constexpr int STG  = 2*SA + 2*SB;
    constexpr int ACH  = BM * (BK/8) / NTH;
    constexpr int BCH  = BK * (BN/8) / NTH;
    static_assert((BM*(BK/8)) % NTH == 0 && (BK*(BN/8)) % NTH == 0, "div");
    static_assert(NT % 2 == 0, "NT even");

    extern __shared__ char dynsm[];
    __nv_bfloat16* smem = reinterpret_cast<__nv_bfloat16*>(dynsm);

    const int tid  = threadIdx.x;
    const int w    = tid >> 5;
    const int lane = tid & 31;
    const int g    = lane >> 2;
    const int t4   = lane & 3;
    const int wm   = (w / (BN/WN)) * WM;
    const int wn   = (w % (BN/WN)) * WN;
    const int brow = blockIdx.x * BM;
    const int bcol = blockIdx.y * BN;
    const int kOff = blockIdx.z * kLen;
    if (OUTM == 0) C += (size_t)blockIdx.z * M * N;
    const bool nedge = (bcol + BN > N);

    const uint32_t sm0 = (uint32_t)__cvta_generic_to_shared(smem);

    float acc[MT][NT][4] = {};

    auto loadTile = [&](int t, int stg) {
        const uint32_t sbase = sm0 + (uint32_t)(stg * STG) * 2;
#pragma unroll
        for (int i = 0; i < ACH; i++) {
            int c = tid + i * NTH;
            int row = c / (BK/8);
            int kc  = (c % (BK/8)) * 8;
            size_t go = (size_t)(brow + row) * lda + kOff + t*BK + kc;
            uint32_t d = sbase + (uint32_t)(row*ASTR + kc) * 2;
            cpasync16(d, Ahi + go);
            cpasync16(d + (uint32_t)SA*2, Alo + go);
        }
#pragma unroll
        for (int i = 0; i < BCH; i++) {
            int c = tid + i * NTH;
            int kr = c / (BN/8);
            int nc = (c % (BN/8)) * 8;
            size_t go = (size_t)(kOff + t*BK + kr) * ldb + bcol + nc;
            uint32_t d = sbase + (uint32_t)(2*SA + kr*BSTR + nc) * 2;
            cpasync16(d, Bhi + go);
            cpasync16(d + (uint32_t)SB*2, Blo + go);
        }
    };

    const int ntiles = kLen / BK;
    const uint32_t a_ro = (uint32_t)(lane & 15) * (ASTR * 2);
    const uint32_t a_co = (uint32_t)((lane >> 4) << 3) * 2;
    const uint32_t b_ro = (uint32_t)(lane & 15) * (BSTR * 2);
    const uint32_t b_co = (uint32_t)(wn + ((lane >> 4) << 3)) * 2;

    const int pre = (ntiles < ST-1) ? ntiles : ST-1;
    for (int s = 0; s < pre; s++) { loadTile(s, s); CP_COMMIT(); }

    int st = 0;
    for (int t = 0; t < ntiles; t++) {
        if (t < ntiles - 1) CP_WAIT1(); else CP_WAIT0();
        __syncthreads();

        const uint32_t sbase = sm0 + (uint32_t)(st * STG) * 2;
#pragma unroll
        for (int kk = 0; kk < BK; kk += 16) {
            uint32_t afh[MT][4], afl[MT][4];
#pragma unroll
            for (int mt = 0; mt < MT; mt++) {
                uint32_t off = sbase + (uint32_t)(wm + mt*16) * (ASTR*2)
                             + a_ro + (uint32_t)kk*2 + a_co;
                ldmx4(afh[mt], off);
                ldmx4(afl[mt], off + (uint32_t)SA*2);
            }
            uint32_t bfh[NT][2], bfl[NT][2];
#pragma unroll
            for (int p = 0; p < NT/2; p++) {
                uint32_t off = sbase + (uint32_t)(2*SA)*2 + (uint32_t)kk * (BSTR*2)
                             + b_ro + (uint32_t)(p*16)*2 + b_co;
                uint32_t r4[4];
                ldmx4t(r4, off);
                bfh[2*p][0] = r4[0]; bfh[2*p][1] = r4[1];
                bfh[2*p+1][0] = r4[2]; bfh[2*p+1][1] = r4[3];
                ldmx4t(r4, off + (uint32_t)SB*2);
                bfl[2*p][0] = r4[0]; bfl[2*p][1] = r4[1];
                bfl[2*p+1][0] = r4[2]; bfl[2*p+1][1] = r4[3];
            }
#pragma unroll
            for (int mt = 0; mt < MT; mt++)
#pragma unroll
                for (int nt = 0; nt < NT; nt++) {
                    mma_bf16(acc[mt][nt], afh[mt], bfl[nt][0], bfl[nt][1]);
                    mma_bf16(acc[mt][nt], afl[mt], bfh[nt][0], bfh[nt][1]);
                    mma_bf16(acc[mt][nt], afh[mt], bfh[nt][0], bfh[nt][1]);
                }
        }
        __syncthreads();
        if (t + ST - 1 < ntiles) {
            loadTile(t + ST - 1, (st + ST - 1) % ST);
            CP_COMMIT();
        }
        st = (st == ST-1) ? 0 : st + 1;
    }

    // ---- epilogue ----
#pragma unroll
    for (int mt = 0; mt < MT; mt++) {
        int r0 = brow + wm + mt*16 + g;
        int r1 = r0 + 8;
#pragma unroll
        for (int nt = 0; nt < NT; nt++) {
            int c0 = bcol + wn + nt*8 + 2*t4;
            float v0 = acc[mt][nt][0], v1 = acc[mt][nt][1];
            float v2 = acc[mt][nt][2], v3 = acc[mt][nt][3];
            if (bias) {
                float b0 = (c0   < N) ? bias[c0]   : 0.f;
                float b1 = (c0+1 < N) ? bias[c0+1] : 0.f;
                v0 += b0; v1 += b1; v2 += b0; v3 += b1;
            }
            if (RELU) {
                v0 = fmaxf(v0, 0.f); v1 = fmaxf(v1, 0.f);
                v2 = fmaxf(v2, 0.f); v3 = fmaxf(v3, 0.f);
            }
            if (OUTM == 1) {
                __nv_bfloat16 h0,l0,h1,l1;
                bsplit(v0,h0,l0); bsplit(v1,h1,l1);
                *reinterpret_cast<__nv_bfloat162*>(Chi + (size_t)r0*N + c0) = __nv_bfloat162(h0,h1);
                *reinterpret_cast<__nv_bfloat162*>(Clo + (size_t)r0*N + c0) = __nv_bfloat162(l0,l1);
                bsplit(v2,h0,l0); bsplit(v3,h1,l1);
                *reinterpret_cast<__nv_bfloat162*>(Chi + (size_t)r1*N + c0) = __nv_bfloat162(h0,h1);
                *reinterpret_cast<__nv_bfloat162*>(Clo + (size_t)r1*N + c0) = __nv_bfloat162(l0,l1);
            } else {
                const bool scalar_store = nedge || (N & 1);
                if (!scalar_store) {
                    float2 p0; p0.x = v0; p0.y = v1;
                    float2 p1; p1.x = v2; p1.y = v3;
                    *reinterpret_cast<float2*>(C + (size_t)r0 * N + c0) = p0;
                    *reinterpret_cast<float2*>(C + (size_t)r1 * N + c0) = p1;
                } else {
                    if (c0   < N) { C[(size_t)r0*N + c0]   = v0; C[(size_t)r1*N + c0]   = v2; }
                    if (c0+1 < N) { C[(size_t)r0*N + c0+1] = v1; C[(size_t)r1*N + c0+1] = v3; }
                }
            }
        }
    }
}

// ---------------------------------------------------------------------------
// LM-head GEMM: 2-pass fp16. A = xf split (Ah+Al), B = Wlm fp16 single plane.
// C = (Ah + Al) @ Bh + bias. Tile 128x128, 8 warps, BK=64, 3-stage cp.async.
// ---------------------------------------------------------------------------
__global__ void __launch_bounds__(256)
lmgemm_kernel(int M, int N, int lda, int ldb, int kLen,
              const __half* __restrict__ Ahi,
              const __half* __restrict__ Alo,
              const __half* __restrict__ Bh,
              const float* __restrict__ bias,
              float* __restrict__ C) {
    constexpr int BM = 128, BN = 128, WM = 64, WN = 32;
    constexpr int BK   = 64;
    constexpr int ST   = 3;
    constexpr int ASTR = BK + 8;      // 72
    constexpr int BSTR = BN + 8;      // 136
    constexpr int NTH  = 256;
    constexpr int MT   = WM / 16;     // 4
    constexpr int NT   = WN / 8;      // 4
    constexpr int SA   = BM * ASTR;   // 9216
    constexpr int SB   = BK * BSTR;   // 8704
    constexpr int STG  = 2*SA + SB;   // 27136 halfs per stage
    constexpr int ACH  = BM * (BK/8) / NTH;   // 4
    constexpr int BCH  = BK * (BN/8) / NTH;   // 4

    extern __shared__ char dynsm[];
    __half* smem = reinterpret_cast<__half*>(dynsm);

    const int tid  = threadIdx.x;
    const int w    = tid >> 5;
    const int lane = tid & 31;
    const int g    = lane >> 2;
    const int t4   = lane & 3;
    const int wm   = (w / (BN/WN)) * WM;   // BN/WN = 4
    const int wn   = (w % (BN/WN)) * WN;
    const int brow = blockIdx.x * BM;
    const int bcol = blockIdx.y * BN;

    const uint32_t sm0 = (uint32_t)__cvta_generic_to_shared(smem);

    float acc[MT][NT][4] = {};

    auto loadTile = [&](int t, int stg) {
        const uint32_t sbase = sm0 + (uint32_t)(stg * STG) * 2;
#pragma unroll
        for (int i = 0; i < ACH; i++) {
            int c = tid + i * NTH;
            int row = c / (BK/8);
            int kc  = (c % (BK/8)) * 8;
            size_t go = (size_t)(brow + row) * lda + t*BK + kc;
            uint32_t d = sbase + (uint32_t)(row*ASTR + kc) * 2;
            cpasync16(d, Ahi + go);
            cpasync16(d + (uint32_t)SA*2, Alo + go);
        }
#pragma unroll
        for (int i = 0; i < BCH; i++) {
            int c = tid + i * NTH;
            int kr = c / (BN/8);
            int nc = (c % (BN/8)) * 8;
            size_t go = (size_t)(t*BK + kr) * ldb + bcol + nc;
            uint32_t d = sbase + (uint32_t)(2*SA + kr*BSTR + nc) * 2;
            cpasync16(d, Bh + go);
        }
    };

    const int ntiles = kLen / BK;  // 4
    const uint32_t a_ro = (uint32_t)(lane & 15) * (ASTR * 2);
    const uint32_t a_co = (uint32_t)((lane >> 4) << 3) * 2;
    const uint32_t b_ro = (uint32_t)(lane & 15) * (BSTR * 2);
    const uint32_t b_co = (uint32_t)(wn + ((lane >> 4) << 3)) * 2;

    const int pre = (ntiles < ST-1) ? ntiles : ST-1;
    for (int s = 0; s < pre; s++) { loadTile(s, s); CP_COMMIT(); }

    int st = 0;
    for (int t = 0; t < ntiles; t++) {
        if (t < ntiles - 1) CP_WAIT1(); else CP_WAIT0();
        __syncthreads();

        const uint32_t sbase = sm0 + (uint32_t)(st * STG) * 2;
#pragma unroll
        for (int kk = 0; kk < BK; kk += 16) {
            uint32_t afh[MT][4], afl[MT][4];
#pragma unroll
            for (int mt = 0; mt < MT; mt++) {
                uint32_t off = sbase + (uint32_t)(wm + mt*16) * (ASTR*2)
                             + a_ro + (uint32_t)kk*2 + a_co;
                ldmx4(afh[mt], off);
                ldmx4(afl[mt], off + (uint32_t)SA*2);
            }
            uint32_t bf[NT][2];
#pragma unroll
            for (int p = 0; p < NT/2; p++) {
                uint32_t off = sbase + (uint32_t)(2*SA)*2 + (uint32_t)kk * (BSTR*2)
                             + b_ro + (uint32_t)(p*16)*2 + b_co;
                uint32_t r4[4];
                ldmx4t(r4, off);
                bf[2*p][0] = r4[0]; bf[2*p][1] = r4[1];
                bf[2*p+1][0] = r4[2]; bf[2*p+1][1] = r4[3];
            }
#pragma unroll
            for (int mt = 0; mt < MT; mt++)
#pragma unroll
                for (int nt = 0; nt < NT; nt++) {
                    mma_f16(acc[mt][nt], afl[mt], bf[nt][0], bf[nt][1]);
                    mma_f16(acc[mt][nt], afh[mt], bf[nt][0], bf[nt][1]);
                }
        }
        __syncthreads();
        if (t + ST - 1 < ntiles) {
            loadTile(t + ST - 1, (st + ST - 1) % ST);
            CP_COMMIT();
        }
        st = (st == ST-1) ? 0 : st + 1;
    }

    // ---- epilogue (N odd -> scalar stores; rows may be 4B-aligned only) ----
#pragma unroll
    for (int mt = 0; mt < MT; mt++) {
        int r0 = brow + wm + mt*16 + g;
        int r1 = r0 + 8;
#pragma unroll
        for (int nt = 0; nt < NT; nt++) {
            int c0 = bcol + wn + nt*8 + 2*t4;
            float v0 = acc[mt][nt][0], v1 = acc[mt][nt][1];
            float v2 = acc[mt][nt][2], v3 = acc[mt][nt][3];
            if (c0 < N) {
                float b0 = bias[c0];
                C[(size_t)r0*N + c0] = v0 + b0;
                C[(size_t)r1*N + c0] = v2 + b0;
            }
            if (c0 + 1 < N) {
                float b1 = bias[c0+1];
                C[(size_t)r0*N + c0+1] = v1 + b1;
                C[(size_t)r1*N + c0+1] = v3 + b1;
            }
        }
    }
}

// ---------------------------------------------------------------------------
// Fused causal attention -> bf16 hi/lo planes
// ---------------------------------------------------------------------------
__global__ void attn_kernel(const float* __restrict__ qkv,
                            __nv_bfloat16* __restrict__ atth,
                            __nv_bfloat16* __restrict__ attl) {
    __shared__ float ks[TT][DD];
    __shared__ float vs[TT][DD];

    int bh = blockIdx.x;
    int b = bh / HH, h = bh % HH;
    int tid = threadIdx.x;

    const float* base = qkv + (size_t)b * TT * 768 + h * DD;
    for (int i = tid; i < TT * DD; i += 128) {
        int s = i >> 5, d = i & 31;
        ks[s][d] = base[s * 768 + 256 + d];
        vs[s][d] = base[s * 768 + 512 + d];
    }

    const int w    = tid >> 5;
    const int lane = tid & 31;
    const int t     = w * 16 + (lane >> 1);
    const int half  = lane & 1;
    const int dbase = half * 16;
    const float scale = 0.17677669529663687f;

    float q[16];
    const float* qp = base + t * 768 + dbase;
#pragma unroll
    for (int dd = 0; dd < 16; dd++) q[dd] = qp[dd] * scale;

    __syncthreads();

    float m = -1e30f, sum = 0.f;
    float o[16];
#pragma unroll
    for (int dd = 0; dd < 16; dd++) o[dd] = 0.f;

    const int tw = w * 16 + 15;
    for (int s = 0; s <= tw; s++) {
        float part = 0.f;
#pragma unroll
        for (int dd = 0; dd < 16; dd++) part += q[dd] * ks[s][dbase + dd];
        float sc = part + __shfl_xor_sync(0xffffffffu, part, 1);
        if (s <= t) {
            float mn   = fmaxf(m, sc);
            float corr = __expf(m - mn);
            float p    = __expf(sc - mn);
            sum = sum * corr + p;
#pragma unroll
            for (int dd = 0; dd < 16; dd++)
                o[dd] = o[dd] * corr + p * vs[s][dbase + dd];
            m = mn;
        }
    }
    float inv = 1.f / sum;
    size_t op = (size_t)(b * TT + t) * EE + h * DD + dbase;
#pragma unroll
    for (int dd = 0; dd < 16; dd++) {
        __nv_bfloat16 hh, ll; bsplit(o[dd] * inv, hh, ll);
        atth[op + dd] = hh; attl[op + dd] = ll;
    }
}

// ---------------------------------------------------------------------------
// Fused: v = x + bias + sum part[s]; out fp32 + bf16 hi/lo of LN(v)
// ---------------------------------------------------------------------------
__global__ void reduce_ln_kernel(const float* __restrict__ xin,
                                 const float* __restrict__ part, int S,
                                 const float* __restrict__ bias,
                                 const float* __restrict__ g,
                                 const float* __restrict__ b,
                                 float* __restrict__ outF,
                                 __nv_bfloat16* __restrict__ outH,
                                 __nv_bfloat16* __restrict__ outL) {
    __shared__ float red1[8];
    __shared__ float red2[8];
    int row = blockIdx.x;
    int c   = threadIdx.x;
    size_t idx = (size_t)row * EE + c;

    float v = xin[idx] + bias[c];
    for (int s = 0; s < S; s++) v += part[(size_t)s * NTOK * EE + idx];

    float sm = v;
#pragma unroll
    for (int o = 16; o > 0; o >>= 1) sm += __shfl_xor_sync(0xffffffffu, sm, o);
    if ((c & 31) == 0) red1[c >> 5] = sm;
    __syncthreads();
    float total = 0.f;
#pragma unroll
    for (int i = 0; i < 8; i++) total += red1[i];
    float mean = total * (1.f / EE);

    float d = v - mean;
    float sq = d * d;
#pragma unroll
    for (int o = 16; o > 0; o >>= 1) sq += __shfl_xor_sync(0xffffffffu, sq, o);
    if ((c & 31) == 0) red2[c >> 5] = sq;
    __syncthreads();
    float tsq = 0.f;
#pragma unroll
    for (int i = 0; i < 8; i++) tsq += red2[i];
    float var = tsq * (1.f / EE);

    float r = d * rsqrtf(var + EPSLN) * g[c] + b[c];
    outF[idx] = r;
    __nv_bfloat16 hh, ll; bsplit(r, hh, ll);
    outH[idx] = hh; outL[idx] = ll;
}

// ---------------------------------------------------------------------------
// Final LayerNorm -> fp16 hi/lo planes (for LM head)
// ---------------------------------------------------------------------------
__global__ void ln_final_kernel(const float* __restrict__ xin,
                                const float* __restrict__ g,
                                const float* __restrict__ b,
                                __half* __restrict__ outH,
                                __half* __restrict__ outL) {
    __shared__ float red1[8];
    __shared__ float red2[8];
    int row = blockIdx.x;
    int c   = threadIdx.x;
    size_t idx = (size_t)row * EE + c;

    float v = xin[idx];
    float sm = v;
#pragma unroll
    for (int o = 16; o > 0; o >>= 1) sm += __shfl_xor_sync(0xffffffffu, sm, o);
    if ((c & 31) == 0) red1[c >> 5] = sm;
    __syncthreads();
    float total = 0.f;
#pragma unroll
    for (int i = 0; i < 8; i++) total += red1[i];
    float mean = total * (1.f / EE);

    float d = v - mean;
    float sq = d * d;
#pragma unroll
    for (int o = 16; o > 0; o >>= 1) sq += __shfl_xor_sync(0xffffffffu, sq, o);
    if ((c & 31) == 0) red2[c >> 5] = sq;
    __syncthreads();
    float tsq = 0.f;
#pragma unroll
    for (int i = 0; i < 8; i++) tsq += red2[i];
    float var = tsq * (1.f / EE);

    float r = d * rsqrtf(var + EPSLN) * g[c] + b[c];
    __half hh, ll; hsplit(r, hh, ll);
    outH[idx] = hh; outL[idx] = ll;
}

// ---------------------------------------------------------------------------
// Host orchestration
// ---------------------------------------------------------------------------
#define SMEM64  110592
#define SMEMLM  162816   // 3 stages * 27136 halfs * 2B

extern "C" void kernel_launch(void* const* d_in, const int* in_sizes, int n_in,
                              void* d_out, int out_size) {
    const int*   ip     = (const int*)  d_in[0];
    const float* tok    = (const float*)d_in[1];
    const float* pos    = (const float*)d_in[2];
    const float* Wq     = (const float*)d_in[3];
    const float* Wk     = (const float*)d_in[4];
    const float* Wv     = (const float*)d_in[5];
    const float* Wo     = (const float*)d_in[6];
    const float* bo     = (const float*)d_in[7];
    const float* ln1g   = (const float*)d_in[8];
    const float* ln1b   = (const float*)d_in[9];
    const float* ln2g   = (const float*)d_in[10];
    const float* ln2b   = (const float*)d_in[11];
    const float* W1     = (const float*)d_in[12];
    const float* b1     = (const float*)d_in[13];
    const float* W2     = (const float*)d_in[14];
    const float* b2     = (const float*)d_in[15];
    const float* lnfg   = (const float*)d_in[16];
    const float* lnfb   = (const float*)d_in[17];
    const float* Wlm    = (const float*)d_in[18];
    const float* blm    = (const float*)d_in[19];
    float*       out    = (float*)d_out;

    cudaFuncSetAttribute(pgemm_kernel<64,64,32,32,false,0>,
                         cudaFuncAttributeMaxDynamicSharedMemorySize, SMEM64);
    cudaFuncSetAttribute(pgemm_kernel<64,64,32,32,true,1>,
                         cudaFuncAttributeMaxDynamicSharedMemorySize, SMEM64);
    cudaFuncSetAttribute(lmgemm_kernel,
                         cudaFuncAttributeMaxDynamicSharedMemorySize, SMEMLM);

    float* buf = nullptr;
    cudaGetSymbolAddress((void**)&buf, g_buf);
    __nv_bfloat16* wb = nullptr;
    cudaGetSymbolAddress((void**)&wb, g_wbuf);
    __nv_bfloat16* ab = nullptr;
    cudaGetSymbolAddress((void**)&ab, g_abuf);
    __half* hb = nullptr;
    cudaGetSymbolAddress((void**)&hb, g_hbuf);

    float* x    = buf + OFF_X;
    float* qkv  = buf + OFF_QKV;
    float* part = buf + OFF_PART;

    embed_kernel<<<NTOK, EE>>>(ip, tok, pos, x, ab + AX_H, ab + AX_L);

    {
        int n = LL * EE * 768;
        prep_wqkv_split<<<(n + 255) / 256, 256>>>(Wq, Wk, Wv);
    }
    { int n = LL*EE*EE;  split_kernel<<<(n+255)/256, 256>>>(Wo, wb+WO_H, wb+WO_L, n); }
    { int n = LL*EE*FFN; split_kernel<<<(n+255)/256, 256>>>(W1, wb+W1_H, wb+W1_L, n); }
    { int n = LL*FFN*EE; split_kernel<<<(n+255)/256, 256>>>(W2, wb+W2_H, wb+W2_L, n); }
    {
        size_t n = (size_t)EE * VPAD;
        prep_wlm_h<<<(unsigned)((n + 255) / 256), 256>>>(Wlm);
    }

    for (int l = 0; l < LL; l++) {
        // QKV: [2048,256]@[256,768] -> fp32
        pgemm_kernel<64,64,32,32,false,0><<<dim3(32,12,1), 128, SMEM64>>>(
            NTOK, 768, EE, 768, 256,
            ab + AX_H, ab + AX_L,
            wb + WT_H + (size_t)l*EE*768, wb + WT_L + (size_t)l*EE*768,
            nullptr, qkv, nullptr, nullptr);

        attn_kernel<<<BB * HH, 128>>>(qkv, ab + AT_H, ab + AT_L);

        // Wo: split-K2 -> fp32 partials
        pgemm_kernel<64,64,32,32,false,0><<<dim3(32,4,2), 128, SMEM64>>>(
            NTOK, EE, EE, EE, 128,
            ab + AT_H, ab + AT_L,
            wb + WO_H + (size_t)l*EE*EE, wb + WO_L + (size_t)l*EE*EE,
            nullptr, part, nullptr, nullptr);
        reduce_ln_kernel<<<NTOK, EE>>>(x, part, 2, bo + l*EE,
                                       ln1g + l*EE, ln1b + l*EE,
                                       x, ab + AX_H, ab + AX_L);

        // FFN1: relu -> bf16 hi/lo planes
        pgemm_kernel<64,64,32,32,true,1><<<dim3(32,16,1), 128, SMEM64>>>(
            NTOK, FFN, EE, FFN, 256,
            ab + AX_H, ab + AX_L,
            wb + W1_H + (size_t)l*EE*FFN, wb + W1_L + (size_t)l*EE*FFN,
            b1 + l*FFN, nullptr, ab + AH_H, ab + AH_L);

        // FFN2: split-K4 -> fp32 partials
        pgemm_kernel<64,64,32,32,false,0><<<dim3(32,4,4), 128, SMEM64>>>(
            NTOK, EE, FFN, EE, 256,
            ab + AH_H, ab + AH_L,
            wb + W2_H + (size_t)l*FFN*EE, wb + W2_L + (size_t)l*FFN*EE,
            nullptr, part, nullptr, nullptr);
        reduce_ln_kernel<<<NTOK, EE>>>(x, part, 4, b2 + l*EE,
                                       ln2g + l*EE, ln2b + l*EE,
                                       x, ab + AX_H, ab + AX_L);
    }

    ln_final_kernel<<<NTOK, EE>>>(x, lnfg, lnfb, hb + XF_H, hb + XF_L);

    // LM head: 2-pass fp16, [2048,256]@[256,50257] + blm
    lmgemm_kernel<<<dim3(16,393,1), 256, SMEMLM>>>(
        NTOK, VOCAB, EE, VPAD, 256,
        hb + XF_H, hb + XF_L, hb + WLMH, blm, out);
}